// round 10
// baseline (speedup 1.0000x reference)
#include <cuda_runtime.h>
#include <math.h>
#include <cstdint>

#define NB 8
#define CDIM 128
#define HH 192
#define WW 192
#define HWD (HH*WW)          // 36864
#define PTOT (NB*HWD)        // 294912
#define LROW 192
#define NROWS (NB*HH)        // 1536
#define BN_EPS 1e-5f

// ---------------- cp.async / ldmatrix / mma helpers (family-portable) ----------------
__device__ __forceinline__ void cpa16(uint32_t s, const float* g) {
    asm volatile("cp.async.ca.shared.global [%0], [%1], 16;" :: "r"(s), "l"(g));
}
#define CP_COMMIT() asm volatile("cp.async.commit_group;" ::: "memory")
#define CP_WAIT0()  asm volatile("cp.async.wait_group 0;" ::: "memory")

__device__ __forceinline__ void ldm4(uint32_t* r, uint32_t addr) {
    asm volatile("ldmatrix.sync.aligned.m8n8.x4.shared.b16 {%0,%1,%2,%3}, [%4];"
                 : "=r"(r[0]), "=r"(r[1]), "=r"(r[2]), "=r"(r[3]) : "r"(addr));
}
__device__ __forceinline__ uint32_t f2tf(uint32_t x) {
    uint32_t y;
    asm("cvt.rna.tf32.f32 %0, %1;" : "=r"(y) : "r"(x));
    return y;
}
__device__ __forceinline__ float tf32r(float x) {
    uint32_t y;
    asm("cvt.rna.tf32.f32 %0, %1;" : "=r"(y) : "f"(x));
    return __uint_as_float(y);
}
__device__ __forceinline__ void mma_tf32(float* d, const uint32_t* a, const uint32_t* b) {
    asm volatile(
        "mma.sync.aligned.m16n8k8.row.col.f32.tf32.tf32.f32 "
        "{%0,%1,%2,%3}, {%4,%5,%6,%7}, {%8,%9}, {%0,%1,%2,%3};"
        : "+f"(d[0]), "+f"(d[1]), "+f"(d[2]), "+f"(d[3])
        : "r"(a[0]), "r"(a[1]), "r"(a[2]), "r"(a[3]), "r"(b[0]), "r"(b[1]));
}

// ---------------- device scratch ----------------
__device__ float g_th [PTOT*CDIM];   // theta (tf32-rounded), later u = f_h
__device__ float g_ph [PTOT*CDIM];   // phi   (tf32-rounded), later v = f_v
__device__ float g_g  [PTOT*CDIM];   // g     (tf32-rounded)
__device__ float g_sch[PTOT*CDIM];
__device__ float g_scv[PTOT*CDIM];
__device__ float g_ah [PTOT*CDIM];   // f_common NHWC before attention; attn-h out after
__device__ float g_av [PTOT*CDIM];

__device__ float g_WtA[5*CDIM*CDIM]; // [mat][d][k] folded, transposed, tf32-rounded
__device__ float g_biasA[5*CDIM];
__device__ float g_Wt3[CDIM*CDIM];
__device__ float g_b3[CDIM];
__device__ float g_Wt5[CDIM*CDIM];
__device__ float g_b5[CDIM];
__device__ float g_WtF[CDIM*2*CDIM];
__device__ float g_ba[CDIM];

// ---------------- BN folding prep ----------------
__global__ void prep_kernel(const float* __restrict__ W7, const float* __restrict__ m7,
                            const float* __restrict__ v7, const float* __restrict__ b7,
                            const float* __restrict__ Wa, const float* __restrict__ ma,
                            const float* __restrict__ va, const float* __restrict__ ba) {
    int t = blockIdx.x * blockDim.x + threadIdx.x;
    int stride = gridDim.x * blockDim.x;
    const int mats[5] = {0, 1, 2, 4, 6};
    for (int idx = t; idx < 5*128*128; idx += stride) {
        int m = idx >> 14, r = idx & 16383, d = r >> 7, k = r & 127;
        int mm = mats[m];
        float rs = rsqrtf(v7[mm*128 + d] + BN_EPS);
        g_WtA[idx] = tf32r(W7[(mm*128 + k)*128 + d] * rs);
        if (k == 0) g_biasA[m*128 + d] = b7[mm*128 + d] - m7[mm*128 + d]*rs;
    }
    for (int idx = t; idx < 128*128; idx += stride) {
        int d = idx >> 7, k = idx & 127;
        float rs3 = rsqrtf(v7[3*128 + d] + BN_EPS);
        float rs5 = rsqrtf(v7[5*128 + d] + BN_EPS);
        g_Wt3[idx] = tf32r(W7[(3*128 + k)*128 + d] * rs3);
        g_Wt5[idx] = tf32r(W7[(5*128 + k)*128 + d] * rs5);
        if (k == 0) {
            g_b3[d] = b7[3*128 + d] - m7[3*128 + d]*rs3;
            g_b5[d] = b7[5*128 + d] - m7[5*128 + d]*rs5;
        }
    }
    for (int idx = t; idx < 128*256; idx += stride) {
        int d = idx >> 8, kk = idx & 255;
        float rs = rsqrtf(va[d] + BN_EPS);
        g_WtF[idx] = tf32r(Wa[kk*128 + d] * rs);
        if (kk == 0) g_ba[d] = ba[d] - ma[d]*rs;
    }
}

// ---------------- NCHW -> NHWC input transpose (into g_ah) ----------------
__global__ void transpose_in(const float* __restrict__ f) {
    __shared__ float tile[32][33];
    int n = blockIdx.z, hw0 = blockIdx.x * 32, c0 = blockIdx.y * 32;
    int tx = threadIdx.x, ty = threadIdx.y;
    const float* src = f + (size_t)n*CDIM*HWD;
#pragma unroll
    for (int i = 0; i < 32; i += 8)
        tile[ty + i][tx] = src[(size_t)(c0 + ty + i)*HWD + hw0 + tx];
    __syncthreads();
    float* dst = g_ah + (size_t)n*HWD*CDIM;
#pragma unroll
    for (int i = 0; i < 32; i += 8)
        dst[(size_t)(hw0 + ty + i)*CDIM + c0 + tx] = tile[tx][ty + i];
}

// ---------------- tf32 tensor-core GEMM (unchanged from R9) ----------------
template<int MODE>
__global__ __launch_bounds__(256, 2) void gemm_kernel(float* __restrict__ out) {
    __shared__ __align__(16) float SA[2][2560];   // [128][20] padded
    __shared__ __align__(16) float SB[2][2560];
    const int tid = threadIdx.x;
    const int wid = tid >> 5, lane = tid & 31;
    int p0, y;
    if (MODE == 0) { y = blockIdx.x; p0 = blockIdx.y * 128; }
    else           { y = blockIdx.y; p0 = blockIdx.x * 128; }
    const int wm = (wid & 3) * 32;
    const int wn = (wid >> 2) * 64;

    const int KT = (MODE == 2) ? 16 : 8;
    const float* Abase0; const float* Bp; int ldk;
    if (MODE == 0)      { Abase0 = g_ah;            Bp = g_WtA + y*16384;   ldk = 128; }
    else if (MODE == 1) { Abase0 = y ? g_av : g_ah; Bp = y ? g_Wt5 : g_Wt3; ldk = 128; }
    else                { Abase0 = g_th;            Bp = g_WtF;             ldk = 256; }

    uint32_t sa_u32 = (uint32_t)__cvta_generic_to_shared(&SA[0][0]);
    uint32_t sb_u32 = (uint32_t)__cvta_generic_to_shared(&SB[0][0]);

    const int tl = lane >> 3, l7 = lane & 7;
    uint32_t a_base[2], b_base[4];
#pragma unroll
    for (int mt = 0; mt < 2; mt++) {
        int arow = wm + mt*16 + ((tl & 1) << 3) + l7;
        int aword = (tl >> 1) << 2;
        a_base[mt] = sa_u32 + (uint32_t)(arow*20 + aword)*4;
    }
#pragma unroll
    for (int ntp = 0; ntp < 4; ntp++) {
        int brow = wn + ntp*16 + ((tl >> 1) << 3) + l7;
        int bword = (tl & 1) << 2;
        b_base[ntp] = sb_u32 + (uint32_t)(brow*20 + bword)*4;
    }

    float acc[2][8][4];
#pragma unroll
    for (int mt = 0; mt < 2; mt++)
#pragma unroll
        for (int nt = 0; nt < 8; nt++)
#pragma unroll
            for (int q = 0; q < 4; q++) acc[mt][nt][q] = 0.f;

    auto load_tile = [&](int t, int buf) {
        int k0 = t * 16;
        const float* asrc;
        if (MODE == 2) asrc = ((t < 8) ? g_th : g_ph) + (size_t)p0*128 + (k0 & 127);
        else           asrc = Abase0 + (size_t)p0*128 + k0;
        uint32_t sab = sa_u32 + (uint32_t)buf*10240;
        uint32_t sbb = sb_u32 + (uint32_t)buf*10240;
#pragma unroll
        for (int i = 0; i < 2; i++) {
            int id = tid + i*256;
            int p = id >> 2, q = id & 3;
            cpa16(sab + (uint32_t)(p*20 + q*4)*4, asrc + (size_t)p*128 + q*4);
        }
        const float* bsrc = Bp + k0;
#pragma unroll
        for (int i = 0; i < 2; i++) {
            int id = tid + i*256;
            int n = id >> 2, q = id & 3;
            cpa16(sbb + (uint32_t)(n*20 + q*4)*4, bsrc + (size_t)n*ldk + q*4);
        }
        CP_COMMIT();
    };

    load_tile(0, 0);
    int buf = 0;
    for (int t = 0; t < KT; t++) {
        CP_WAIT0();
        __syncthreads();
        if (t + 1 < KT) load_tile(t + 1, buf ^ 1);

        uint32_t boff = (uint32_t)buf * 10240;
#pragma unroll
        for (int s = 0; s < 2; s++) {
            uint32_t a[2][4], b[4][4];
#pragma unroll
            for (int mt = 0; mt < 2; mt++) {
                ldm4(a[mt], a_base[mt] + boff + s*32);
#pragma unroll
                for (int q = 0; q < 4; q++) a[mt][q] = f2tf(a[mt][q]);
            }
#pragma unroll
            for (int ntp = 0; ntp < 4; ntp++)
                ldm4(b[ntp], b_base[ntp] + boff + s*32);
#pragma unroll
            for (int mt = 0; mt < 2; mt++)
#pragma unroll
                for (int ntp = 0; ntp < 4; ntp++) {
                    mma_tf32(acc[mt][ntp*2 + 0], a[mt], &b[ntp][0]);
                    mma_tf32(acc[mt][ntp*2 + 1], a[mt], &b[ntp][2]);
                }
        }
        __syncthreads();
        buf ^= 1;
    }

    if (MODE == 2) {
        const float* biasp = g_ba;
        float* SP = &SA[0][0];
        const int n_img = p0 / HWD, hw0 = p0 % HWD;
        float* obase = out + (size_t)n_img*CDIM*HWD + hw0;
#pragma unroll
        for (int ch = 0; ch < 2; ch++) {
            if ((wid >> 2) == ch) {
#pragma unroll
                for (int nt = 0; nt < 8; nt++) {
                    int cb = nt*8 + (lane & 3)*2;
                    float b0 = biasp[ch*64 + cb], b1 = biasp[ch*64 + cb + 1];
#pragma unroll
                    for (int mt = 0; mt < 2; mt++)
#pragma unroll
                        for (int half = 0; half < 2; half++) {
                            int row = wm + (lane >> 2) + mt*16 + half*8;
                            SP[cb*129 + row]     = fmaxf(acc[mt][nt][half*2 + 0] + b0, 0.f);
                            SP[(cb+1)*129 + row] = fmaxf(acc[mt][nt][half*2 + 1] + b1, 0.f);
                        }
                }
            }
            __syncthreads();
#pragma unroll
            for (int t2 = 0; t2 < 32; t2++) {
                int id = tid + t2*256;
                int c = id >> 7, pix = id & 127;
                obase[(size_t)(ch*64 + c)*HWD + pix] = SP[c*129 + pix];
            }
            __syncthreads();
        }
        return;
    }

    float* outp; const float* biasp; const float* addp = nullptr; bool relu, rnd;
    if (MODE == 0) {
        outp = (y==0) ? g_th : (y==1) ? g_ph : (y==2) ? g_g : (y==3) ? g_sch : g_scv;
        biasp = g_biasA + y*128;
        relu = (y < 3);
        rnd  = (y < 3);
    } else {
        outp = y ? g_ph : g_th;
        biasp = y ? g_b5 : g_b3;
        addp  = y ? g_scv : g_sch;
        relu = true; rnd = false;
    }

    const int rbase = p0 + wm + (lane >> 2);
#pragma unroll
    for (int nt = 0; nt < 8; nt++) {
        int cb = wn + nt*8 + (lane & 3)*2;
        float b0 = biasp[cb], b1 = biasp[cb + 1];
#pragma unroll
        for (int mt = 0; mt < 2; mt++) {
#pragma unroll
            for (int half = 0; half < 2; half++) {
                int row = rbase + mt*16 + half*8;
                size_t ro = (size_t)row*128 + cb;
                float v0 = acc[mt][nt][half*2 + 0] + b0;
                float v1 = acc[mt][nt][half*2 + 1] + b1;
                if (MODE == 1) {
                    float2 ad = *(const float2*)(addp + ro);
                    v0 += ad.x; v1 += ad.y;
                }
                if (relu) { v0 = fmaxf(v0, 0.f); v1 = fmaxf(v1, 0.f); }
                if (rnd)  { v0 = tf32r(v0); v1 = tf32r(v1); }
                *(float2*)(outp + ro) = make_float2(v0, v1);
            }
        }
    }
}

// ---------------- axial attention: FA2-style, P resident in registers ----------------
// 128 threads, 4 warps; each warp owns 16 full S rows (16x64).
// K stored with rows permuted within groups of 8 (slot s <- row rho[s]) so the
// S accumulator fragments feed the PV mma A-operand directly ((c0,c2,c1,c3))
// against NATURAL-order V rows.  No Ps buffer, softmax fully in registers.
// smem: Qs [64][132] rowmaj | KV union (K [64][132] rowmaj / V [128][68] cmaj)
__global__ __launch_bounds__(128, 3) void attn_kernel() {
    extern __shared__ float sm[];
    float* Qs = sm;                   // 8448 floats
    float* KV = Qs + 8448;            // 8704 floats

    const int tid = threadIdx.x;
    const int wid = tid >> 5, lane = tid & 31;
    const int q0 = blockIdx.x * 64;
    const int brow_idx = blockIdx.y;
    const int dir = blockIdx.z;

    size_t base; int stride;
    if (dir == 0) { base = (size_t)brow_idx * LROW * CDIM; stride = CDIM; }
    else {
        int n = brow_idx / WW, w = brow_idx % WW;
        base = (size_t)n*HH*WW*CDIM + (size_t)w*CDIM;
        stride = WW*CDIM;
    }
    const float* thp = g_th + base;
    const float* php = g_ph + base;
    const float* gp  = g_g  + base;
    float* outp = (dir == 0 ? g_ah : g_av) + base;

    uint32_t qs_u = (uint32_t)__cvta_generic_to_shared(Qs);
    uint32_t kv_u = (uint32_t)__cvta_generic_to_shared(KV);

    // Q fill via cp.async (tf32-rounded in gmem): 2048 chunks / 128 threads
#pragma unroll
    for (int t = 0; t < 16; t++) {
        int id = tid + t*128;
        int i = id >> 5, q = id & 31;
        cpa16(qs_u + (uint32_t)(i*132 + q*4)*4, thp + (size_t)(q0 + i)*stride + q*4);
    }
    CP_COMMIT();

    const int tl = lane >> 3, l7 = lane & 7;
    const int wm = wid * 16;

    uint32_t sa_base = qs_u + (uint32_t)((wm + ((tl & 1) << 3) + l7)*132 + ((tl >> 1) << 2))*4;
    uint32_t sbK[4];
#pragma unroll
    for (int ntp = 0; ntp < 4; ntp++)
        sbK[ntp] = kv_u + (uint32_t)((ntp*16 + ((tl >> 1) << 3) + l7)*132 + ((tl & 1) << 2))*4;
    uint32_t sbV[8];
#pragma unroll
    for (int ntp = 0; ntp < 8; ntp++)
        sbV[ntp] = kv_u + (uint32_t)((ntp*16 + ((tl >> 1) << 3) + l7)*68 + ((tl & 1) << 2))*4;

    float o[16][4];
#pragma unroll
    for (int nt = 0; nt < 16; nt++)
#pragma unroll
        for (int q = 0; q < 4; q++) o[nt][q] = 0.f;
    float m0 = -1e30f, m1 = -1e30f, l0 = 0.f, l1 = 0.f;
    const float scale = 0.08838834764831845f;   // 1/sqrt(128)

    const int rho[8] = {0, 4, 1, 5, 2, 6, 3, 7};   // K slot s <- row rho[s%8]

    for (int kb = 0; kb < LROW; kb += 64) {
        __syncthreads();   // prior PV's V reads done -> KV writable
        // K fill, permuted rows within groups of 8
#pragma unroll
        for (int t = 0; t < 16; t++) {
            int id = tid + t*128;
            int s = id >> 5, q = id & 31;
            int jsrc = (s & ~7) | rho[s & 7];
            cpa16(kv_u + (uint32_t)(s*132 + q*4)*4, php + (size_t)(kb + jsrc)*stride + q*4);
        }
        CP_COMMIT();
        CP_WAIT0();        // also covers Q on first chunk
        __syncthreads();

        // S' = Q K'^T  (warp tile 16x64, 16 k8 steps)
        float sacc[8][4];
#pragma unroll
        for (int nt = 0; nt < 8; nt++)
#pragma unroll
            for (int q = 0; q < 4; q++) sacc[nt][q] = 0.f;
#pragma unroll
        for (int s = 0; s < 16; s++) {
            uint32_t a[4];
            ldm4(a, sa_base + s*32);
#pragma unroll
            for (int ntp = 0; ntp < 4; ntp++) {
                uint32_t b[4];
                ldm4(b, sbK[ntp] + s*32);
                mma_tf32(sacc[ntp*2 + 0], a, &b[0]);
                mma_tf32(sacc[ntp*2 + 1], a, &b[2]);
            }
        }
        __syncthreads();   // all warps' K reads done -> KV writable for V

        // V fill: c-major KV[c][68], float4-over-j (natural row order)
#pragma unroll
        for (int t = 0; t < 16; t++) {
            int j0 = t * 4;
            float4 v;
            v.x = gp[(size_t)(kb + j0 + 0)*stride + tid];
            v.y = gp[(size_t)(kb + j0 + 1)*stride + tid];
            v.z = gp[(size_t)(kb + j0 + 2)*stride + tid];
            v.w = gp[(size_t)(kb + j0 + 3)*stride + tid];
            *(float4*)&KV[tid*68 + j0] = v;
        }

        // register-resident online softmax (rows g=lane>>2 and g+8)
        float r0 = -1e30f, r1 = -1e30f;
#pragma unroll
        for (int nt = 0; nt < 8; nt++) {
            sacc[nt][0] *= scale; sacc[nt][1] *= scale;
            sacc[nt][2] *= scale; sacc[nt][3] *= scale;
            r0 = fmaxf(r0, fmaxf(sacc[nt][0], sacc[nt][1]));
            r1 = fmaxf(r1, fmaxf(sacc[nt][2], sacc[nt][3]));
        }
        r0 = fmaxf(r0, __shfl_xor_sync(0xffffffffu, r0, 1));
        r0 = fmaxf(r0, __shfl_xor_sync(0xffffffffu, r0, 2));
        r1 = fmaxf(r1, __shfl_xor_sync(0xffffffffu, r1, 1));
        r1 = fmaxf(r1, __shfl_xor_sync(0xffffffffu, r1, 2));
        float mn0 = fmaxf(m0, r0), mn1 = fmaxf(m1, r1);
        float al0 = __expf(m0 - mn0), al1 = __expf(m1 - mn1);
        float s0 = 0.f, s1 = 0.f;
#pragma unroll
        for (int nt = 0; nt < 8; nt++) {
            float e0 = tf32r(__expf(sacc[nt][0] - mn0));
            float e1 = tf32r(__expf(sacc[nt][1] - mn0));
            float e2 = tf32r(__expf(sacc[nt][2] - mn1));
            float e3 = tf32r(__expf(sacc[nt][3] - mn1));
            sacc[nt][0] = e0; sacc[nt][1] = e1; sacc[nt][2] = e2; sacc[nt][3] = e3;
            s0 += e0 + e1; s1 += e2 + e3;
        }
        s0 += __shfl_xor_sync(0xffffffffu, s0, 1);
        s0 += __shfl_xor_sync(0xffffffffu, s0, 2);
        s1 += __shfl_xor_sync(0xffffffffu, s1, 1);
        s1 += __shfl_xor_sync(0xffffffffu, s1, 2);
        l0 = l0*al0 + s0; l1 = l1*al1 + s1;
        m0 = mn0; m1 = mn1;
#pragma unroll
        for (int nt = 0; nt < 16; nt++) {
            o[nt][0] *= al0; o[nt][1] *= al0;
            o[nt][2] *= al1; o[nt][3] *= al1;
        }
        __syncthreads();   // V visible

        // O += P V  (P direct from sacc regs; k-step s uses S' tile s)
#pragma unroll
        for (int s = 0; s < 8; s++) {
            uint32_t a[4];
            a[0] = __float_as_uint(sacc[s][0]);
            a[1] = __float_as_uint(sacc[s][2]);
            a[2] = __float_as_uint(sacc[s][1]);
            a[3] = __float_as_uint(sacc[s][3]);
#pragma unroll
            for (int ntp = 0; ntp < 8; ntp++) {
                uint32_t b[4];
                ldm4(b, sbV[ntp] + s*32);
                mma_tf32(o[ntp*2 + 0], a, &b[0]);
                mma_tf32(o[ntp*2 + 1], a, &b[2]);
            }
        }
    }

    {
        float inv0 = 1.f / l0;
        float inv1 = 1.f / l1;
        int r0r = q0 + wm + (lane >> 2);
        int cb0 = (lane & 3) * 2;
#pragma unroll
        for (int nt = 0; nt < 16; nt++) {
            int cb = nt*8 + cb0;
            *(float2*)&outp[(size_t)r0r*stride + cb] =
                make_float2(o[nt][0]*inv0, o[nt][1]*inv0);
            *(float2*)&outp[(size_t)(r0r + 8)*stride + cb] =
                make_float2(o[nt][2]*inv1, o[nt][3]*inv1);
        }
    }
}

// ---------------- launch ----------------
extern "C" void kernel_launch(void* const* d_in, const int* in_sizes, int n_in,
                              void* d_out, int out_size) {
    const float* f  = (const float*)d_in[0];
    const float* W7 = (const float*)d_in[1];
    const float* m7 = (const float*)d_in[2];
    const float* v7 = (const float*)d_in[3];
    const float* b7 = (const float*)d_in[4];
    const float* Wa = (const float*)d_in[5];
    const float* ma = (const float*)d_in[6];
    const float* va = (const float*)d_in[7];
    const float* ba = (const float*)d_in[8];
    float* out = (float*)d_out;

    prep_kernel<<<64, 256>>>(W7, m7, v7, b7, Wa, ma, va, ba);

    transpose_in<<<dim3(HWD/32, CDIM/32, NB), dim3(32, 8)>>>(f);

    gemm_kernel<0><<<dim3(5, PTOT/128), 256>>>(nullptr);

    int smem_bytes = (8448 + 8704) * 4;   // 68608
    cudaFuncSetAttribute(attn_kernel, cudaFuncAttributeMaxDynamicSharedMemorySize, smem_bytes);
    attn_kernel<<<dim3(LROW/64, NROWS, 2), 128, smem_bytes>>>();

    gemm_kernel<1><<<dim3(PTOT/128, 2), 256>>>(nullptr);

    gemm_kernel<2><<<dim3(PTOT/128, 1), 256>>>(out);
}

// round 11
// speedup vs baseline: 1.0370x; 1.0370x over previous
#include <cuda_runtime.h>
#include <math.h>
#include <cstdint>

#define NB 8
#define CDIM 128
#define HH 192
#define WW 192
#define HWD (HH*WW)          // 36864
#define PTOT (NB*HWD)        // 294912
#define LROW 192
#define NROWS (NB*HH)        // 1536
#define BN_EPS 1e-5f

// ---------------- cp.async / ldmatrix / mma helpers (family-portable) ----------------
__device__ __forceinline__ void cpa16(uint32_t s, const float* g) {
    asm volatile("cp.async.ca.shared.global [%0], [%1], 16;" :: "r"(s), "l"(g));
}
#define CP_COMMIT() asm volatile("cp.async.commit_group;" ::: "memory")
#define CP_WAIT0()  asm volatile("cp.async.wait_group 0;" ::: "memory")

__device__ __forceinline__ void ldm4(uint32_t* r, uint32_t addr) {
    asm volatile("ldmatrix.sync.aligned.m8n8.x4.shared.b16 {%0,%1,%2,%3}, [%4];"
                 : "=r"(r[0]), "=r"(r[1]), "=r"(r[2]), "=r"(r[3]) : "r"(addr));
}
__device__ __forceinline__ float tf32r(float x) {
    uint32_t y;
    asm("cvt.rna.tf32.f32 %0, %1;" : "=r"(y) : "f"(x));
    return __uint_as_float(y);
}
__device__ __forceinline__ void mma_tf32(float* d, const uint32_t* a, const uint32_t* b) {
    asm volatile(
        "mma.sync.aligned.m16n8k8.row.col.f32.tf32.tf32.f32 "
        "{%0,%1,%2,%3}, {%4,%5,%6,%7}, {%8,%9}, {%0,%1,%2,%3};"
        : "+f"(d[0]), "+f"(d[1]), "+f"(d[2]), "+f"(d[3])
        : "r"(a[0]), "r"(a[1]), "r"(a[2]), "r"(a[3]), "r"(b[0]), "r"(b[1]));
}

// ---------------- device scratch ----------------
__device__ float g_th [PTOT*CDIM];   // theta (tf32-rounded), later u = f_h (tf32-rounded)
__device__ float g_ph [PTOT*CDIM];   // phi   (tf32-rounded), later v = f_v (tf32-rounded)
__device__ float g_g  [PTOT*CDIM];   // g     (tf32-rounded)
__device__ float g_sch[PTOT*CDIM];
__device__ float g_scv[PTOT*CDIM];
__device__ float g_ah [PTOT*CDIM];   // f_common NHWC (tf32-rounded); attn-h out after
__device__ float g_av [PTOT*CDIM];

__device__ float g_WtA[5*CDIM*CDIM]; // [mat][d][k] folded, transposed, tf32-rounded
__device__ float g_biasA[5*CDIM];
__device__ float g_Wt3[CDIM*CDIM];
__device__ float g_b3[CDIM];
__device__ float g_Wt5[CDIM*CDIM];
__device__ float g_b5[CDIM];
__device__ float g_WtF[CDIM*2*CDIM];
__device__ float g_ba[CDIM];

// ---------------- BN folding prep ----------------
__global__ void prep_kernel(const float* __restrict__ W7, const float* __restrict__ m7,
                            const float* __restrict__ v7, const float* __restrict__ b7,
                            const float* __restrict__ Wa, const float* __restrict__ ma,
                            const float* __restrict__ va, const float* __restrict__ ba) {
    int t = blockIdx.x * blockDim.x + threadIdx.x;
    int stride = gridDim.x * blockDim.x;
    const int mats[5] = {0, 1, 2, 4, 6};
    for (int idx = t; idx < 5*128*128; idx += stride) {
        int m = idx >> 14, r = idx & 16383, d = r >> 7, k = r & 127;
        int mm = mats[m];
        float rs = rsqrtf(v7[mm*128 + d] + BN_EPS);
        g_WtA[idx] = tf32r(W7[(mm*128 + k)*128 + d] * rs);
        if (k == 0) g_biasA[m*128 + d] = b7[mm*128 + d] - m7[mm*128 + d]*rs;
    }
    for (int idx = t; idx < 128*128; idx += stride) {
        int d = idx >> 7, k = idx & 127;
        float rs3 = rsqrtf(v7[3*128 + d] + BN_EPS);
        float rs5 = rsqrtf(v7[5*128 + d] + BN_EPS);
        g_Wt3[idx] = tf32r(W7[(3*128 + k)*128 + d] * rs3);
        g_Wt5[idx] = tf32r(W7[(5*128 + k)*128 + d] * rs5);
        if (k == 0) {
            g_b3[d] = b7[3*128 + d] - m7[3*128 + d]*rs3;
            g_b5[d] = b7[5*128 + d] - m7[5*128 + d]*rs5;
        }
    }
    for (int idx = t; idx < 128*256; idx += stride) {
        int d = idx >> 8, kk = idx & 255;
        float rs = rsqrtf(va[d] + BN_EPS);
        g_WtF[idx] = tf32r(Wa[kk*128 + d] * rs);
        if (kk == 0) g_ba[d] = ba[d] - ma[d]*rs;
    }
}

// ---------------- NCHW -> NHWC input transpose (into g_ah, tf32-rounded) ----------------
__global__ void transpose_in(const float* __restrict__ f) {
    __shared__ float tile[32][33];
    int n = blockIdx.z, hw0 = blockIdx.x * 32, c0 = blockIdx.y * 32;
    int tx = threadIdx.x, ty = threadIdx.y;
    const float* src = f + (size_t)n*CDIM*HWD;
#pragma unroll
    for (int i = 0; i < 32; i += 8)
        tile[ty + i][tx] = src[(size_t)(c0 + ty + i)*HWD + hw0 + tx];
    __syncthreads();
    float* dst = g_ah + (size_t)n*HWD*CDIM;
#pragma unroll
    for (int i = 0; i < 32; i += 8)
        dst[(size_t)(hw0 + ty + i)*CDIM + c0 + tx] = tf32r(tile[tx][ty + i]);
}

// ---------------- tf32 tensor-core GEMM ----------------
// All A operands are tf32-pre-rounded in gmem -> no cvt in mainloop.
// MODE 0: grid (5, pixblocks): y = mat. Outputs th/ph/g tf32-rounded; sch/scv raw.
// MODE 1: grid (pixblocks, 2). +shortcut, relu, outputs tf32-rounded (feed MODE2 A).
// MODE 2: grid (pixblocks, 1). K=256; direct NCHW output via smem transpose.
template<int MODE>
__global__ __launch_bounds__(256, 2) void gemm_kernel(float* __restrict__ out) {
    __shared__ __align__(16) float SA[2][2560];   // [128][20] padded
    __shared__ __align__(16) float SB[2][2560];
    const int tid = threadIdx.x;
    const int wid = tid >> 5, lane = tid & 31;
    int p0, y;
    if (MODE == 0) { y = blockIdx.x; p0 = blockIdx.y * 128; }
    else           { y = blockIdx.y; p0 = blockIdx.x * 128; }
    const int wm = (wid & 3) * 32;
    const int wn = (wid >> 2) * 64;

    const int KT = (MODE == 2) ? 16 : 8;
    const float* Abase0; const float* Bp; int ldk;
    if (MODE == 0)      { Abase0 = g_ah;            Bp = g_WtA + y*16384;   ldk = 128; }
    else if (MODE == 1) { Abase0 = y ? g_av : g_ah; Bp = y ? g_Wt5 : g_Wt3; ldk = 128; }
    else                { Abase0 = g_th;            Bp = g_WtF;             ldk = 256; }

    uint32_t sa_u32 = (uint32_t)__cvta_generic_to_shared(&SA[0][0]);
    uint32_t sb_u32 = (uint32_t)__cvta_generic_to_shared(&SB[0][0]);

    const int tl = lane >> 3, l7 = lane & 7;
    uint32_t a_base[2], b_base[4];
#pragma unroll
    for (int mt = 0; mt < 2; mt++) {
        int arow = wm + mt*16 + ((tl & 1) << 3) + l7;
        int aword = (tl >> 1) << 2;
        a_base[mt] = sa_u32 + (uint32_t)(arow*20 + aword)*4;
    }
#pragma unroll
    for (int ntp = 0; ntp < 4; ntp++) {
        int brow = wn + ntp*16 + ((tl >> 1) << 3) + l7;
        int bword = (tl & 1) << 2;
        b_base[ntp] = sb_u32 + (uint32_t)(brow*20 + bword)*4;
    }

    float acc[2][8][4];
#pragma unroll
    for (int mt = 0; mt < 2; mt++)
#pragma unroll
        for (int nt = 0; nt < 8; nt++)
#pragma unroll
            for (int q = 0; q < 4; q++) acc[mt][nt][q] = 0.f;

    auto load_tile = [&](int t, int buf) {
        int k0 = t * 16;
        const float* asrc;
        if (MODE == 2) asrc = ((t < 8) ? g_th : g_ph) + (size_t)p0*128 + (k0 & 127);
        else           asrc = Abase0 + (size_t)p0*128 + k0;
        uint32_t sab = sa_u32 + (uint32_t)buf*10240;
        uint32_t sbb = sb_u32 + (uint32_t)buf*10240;
#pragma unroll
        for (int i = 0; i < 2; i++) {
            int id = tid + i*256;
            int p = id >> 2, q = id & 3;
            cpa16(sab + (uint32_t)(p*20 + q*4)*4, asrc + (size_t)p*128 + q*4);
        }
        const float* bsrc = Bp + k0;
#pragma unroll
        for (int i = 0; i < 2; i++) {
            int id = tid + i*256;
            int n = id >> 2, q = id & 3;
            cpa16(sbb + (uint32_t)(n*20 + q*4)*4, bsrc + (size_t)n*ldk + q*4);
        }
        CP_COMMIT();
    };

    load_tile(0, 0);
    int buf = 0;
    for (int t = 0; t < KT; t++) {
        CP_WAIT0();
        __syncthreads();
        if (t + 1 < KT) load_tile(t + 1, buf ^ 1);

        uint32_t boff = (uint32_t)buf * 10240;
#pragma unroll
        for (int s = 0; s < 2; s++) {
            uint32_t a[2][4], b[4][4];
#pragma unroll
            for (int mt = 0; mt < 2; mt++)
                ldm4(a[mt], a_base[mt] + boff + s*32);
#pragma unroll
            for (int ntp = 0; ntp < 4; ntp++)
                ldm4(b[ntp], b_base[ntp] + boff + s*32);
#pragma unroll
            for (int mt = 0; mt < 2; mt++)
#pragma unroll
                for (int ntp = 0; ntp < 4; ntp++) {
                    mma_tf32(acc[mt][ntp*2 + 0], a[mt], &b[ntp][0]);
                    mma_tf32(acc[mt][ntp*2 + 1], a[mt], &b[ntp][2]);
                }
        }
        __syncthreads();
        buf ^= 1;
    }

    if (MODE == 2) {
        const float* biasp = g_ba;
        float* SP = &SA[0][0];
        const int n_img = p0 / HWD, hw0 = p0 % HWD;
        float* obase = out + (size_t)n_img*CDIM*HWD + hw0;
#pragma unroll
        for (int ch = 0; ch < 2; ch++) {
            if ((wid >> 2) == ch) {
#pragma unroll
                for (int nt = 0; nt < 8; nt++) {
                    int cb = nt*8 + (lane & 3)*2;
                    float b0 = biasp[ch*64 + cb], b1 = biasp[ch*64 + cb + 1];
#pragma unroll
                    for (int mt = 0; mt < 2; mt++)
#pragma unroll
                        for (int half = 0; half < 2; half++) {
                            int row = wm + (lane >> 2) + mt*16 + half*8;
                            SP[cb*129 + row]     = fmaxf(acc[mt][nt][half*2 + 0] + b0, 0.f);
                            SP[(cb+1)*129 + row] = fmaxf(acc[mt][nt][half*2 + 1] + b1, 0.f);
                        }
                }
            }
            __syncthreads();
#pragma unroll
            for (int t2 = 0; t2 < 32; t2++) {
                int id = tid + t2*256;
                int c = id >> 7, pix = id & 127;
                obase[(size_t)(ch*64 + c)*HWD + pix] = SP[c*129 + pix];
            }
            __syncthreads();
        }
        return;
    }

    float* outp; const float* biasp; const float* addp = nullptr; bool relu, rnd;
    if (MODE == 0) {
        outp = (y==0) ? g_th : (y==1) ? g_ph : (y==2) ? g_g : (y==3) ? g_sch : g_scv;
        biasp = g_biasA + y*128;
        relu = (y < 3);
        rnd  = (y < 3);    // th/ph/g feed attention as tf32 operands
    } else {
        outp = y ? g_ph : g_th;
        biasp = y ? g_b5 : g_b3;
        addp  = y ? g_scv : g_sch;
        relu = true;
        rnd  = true;       // u/v feed MODE2 as tf32 A operands
    }

    const int rbase = p0 + wm + (lane >> 2);
#pragma unroll
    for (int nt = 0; nt < 8; nt++) {
        int cb = wn + nt*8 + (lane & 3)*2;
        float b0 = biasp[cb], b1 = biasp[cb + 1];
#pragma unroll
        for (int mt = 0; mt < 2; mt++) {
#pragma unroll
            for (int half = 0; half < 2; half++) {
                int row = rbase + mt*16 + half*8;
                size_t ro = (size_t)row*128 + cb;
                float v0 = acc[mt][nt][half*2 + 0] + b0;
                float v1 = acc[mt][nt][half*2 + 1] + b1;
                if (MODE == 1) {
                    float2 ad = *(const float2*)(addp + ro);
                    v0 += ad.x; v1 += ad.y;
                }
                if (relu) { v0 = fmaxf(v0, 0.f); v1 = fmaxf(v1, 0.f); }
                if (rnd)  { v0 = tf32r(v0); v1 = tf32r(v1); }
                *(float2*)(outp + ro) = make_float2(v0, v1);
            }
        }
    }
}

// ---------------- axial attention: flash-style on mma.sync tf32 (R9 shape, 8 warps) ----------------
// smem: Qs [64][132] | KV union (K [64][132] rowmaj / V [128][68] cmaj) |
//       Ps [64][68] | red_alpha[64] | red_l[64]
// Output tf32-rounded (feeds MODE1 as tf32 A operand).
__global__ __launch_bounds__(256, 2) void attn_kernel() {
    extern __shared__ float sm[];
    float* Qs = sm;                   // 8448 floats
    float* KV = Qs + 8448;            // 8704 floats
    float* Ps = KV + 8704;            // 4352
    float* red_alpha = Ps + 4352;     // 64
    float* red_l = red_alpha + 64;    // 64

    const int tid = threadIdx.x;
    const int wid = tid >> 5, lane = tid & 31;
    const int q0 = blockIdx.x * 64;
    const int brow_idx = blockIdx.y;
    const int dir = blockIdx.z;

    size_t base; int stride;
    if (dir == 0) { base = (size_t)brow_idx * LROW * CDIM; stride = CDIM; }
    else {
        int n = brow_idx / WW, w = brow_idx % WW;
        base = (size_t)n*HH*WW*CDIM + (size_t)w*CDIM;
        stride = WW*CDIM;
    }
    const float* thp = g_th + base;
    const float* php = g_ph + base;
    const float* gp  = g_g  + base;
    float* outp = (dir == 0 ? g_ah : g_av) + base;

    uint32_t qs_u = (uint32_t)__cvta_generic_to_shared(Qs);
    uint32_t kv_u = (uint32_t)__cvta_generic_to_shared(KV);
    uint32_t ps_u = (uint32_t)__cvta_generic_to_shared(Ps);

    // Q load via cp.async (tf32-rounded in gmem)
#pragma unroll
    for (int t = 0; t < 8; t++) {
        int id = tid + t*256;                   // 2048 16B chunks
        int i = id >> 5, q = id & 31;
        cpa16(qs_u + (uint32_t)(i*132 + q*4)*4, thp + (size_t)(q0 + i)*stride + q*4);
    }
    CP_COMMIT();

    const int tl = lane >> 3, l7 = lane & 7;
    const int wm  = (wid & 3) * 16;
    const int wns = (wid >> 2) * 32;
    const int wnp = (wid >> 2) * 64;

    uint32_t sa_base = qs_u + (uint32_t)((wm + ((tl & 1) << 3) + l7)*132 + ((tl >> 1) << 2))*4;
    uint32_t sb_base[2];
#pragma unroll
    for (int ntp = 0; ntp < 2; ntp++)
        sb_base[ntp] = kv_u + (uint32_t)((wns + ntp*16 + ((tl >> 1) << 3) + l7)*132 + ((tl & 1) << 2))*4;
    uint32_t pa_base = ps_u + (uint32_t)((wm + ((tl & 1) << 3) + l7)*68 + ((tl >> 1) << 2))*4;
    uint32_t pb_base[4];
#pragma unroll
    for (int ntp = 0; ntp < 4; ntp++)
        pb_base[ntp] = kv_u + (uint32_t)((wnp + ntp*16 + ((tl >> 1) << 3) + l7)*68 + ((tl & 1) << 2))*4;

    const int grow = tid >> 2, slane = tid & 3;
    const int frow = lane >> 2, fcol2 = (lane & 3)*2;

    float o[8][4];
#pragma unroll
    for (int nt = 0; nt < 8; nt++)
#pragma unroll
        for (int q = 0; q < 4; q++) o[nt][q] = 0.f;
    float m_run = -1e30f, l_run = 0.f;
    const float scale = 0.08838834764831845f;   // 1/sqrt(128)

    for (int kb = 0; kb < LROW; kb += 64) {
        __syncthreads();   // prior chunk's PV reads of KV(V) done
        // K chunk via cp.async -> row-major KV[j][132]
#pragma unroll
        for (int t = 0; t < 8; t++) {
            int id = tid + t*256;
            int j = id >> 5, q = id & 31;
            cpa16(kv_u + (uint32_t)(j*132 + q*4)*4, php + (size_t)(kb + j)*stride + q*4);
        }
        CP_COMMIT();
        CP_WAIT0();        // also covers Q on first chunk
        __syncthreads();

        // S = Q K^T (warp tile 16x32, 16 k8 steps)
        float sacc[4][4];
#pragma unroll
        for (int nt = 0; nt < 4; nt++)
#pragma unroll
            for (int q = 0; q < 4; q++) sacc[nt][q] = 0.f;
#pragma unroll
        for (int s = 0; s < 16; s++) {
            uint32_t a[4], b0[4], b1[4];
            ldm4(a, sa_base + s*32);
            ldm4(b0, sb_base[0] + s*32);
            ldm4(b1, sb_base[1] + s*32);
            mma_tf32(sacc[0], a, &b0[0]);
            mma_tf32(sacc[1], a, &b0[2]);
            mma_tf32(sacc[2], a, &b1[0]);
            mma_tf32(sacc[3], a, &b1[2]);
        }
#pragma unroll
        for (int nt = 0; nt < 4; nt++) {
            int cb = wns + nt*8 + fcol2;
            *(float2*)&Ps[(wm + frow)*68 + cb] =
                make_float2(sacc[nt][0]*scale, sacc[nt][1]*scale);
            *(float2*)&Ps[(wm + 8 + frow)*68 + cb] =
                make_float2(sacc[nt][2]*scale, sacc[nt][3]*scale);
        }
        __syncthreads();   // S visible; K reads done -> KV free for V

        // V chunk -> c-major KV[c][68] via float4-over-j writes
#pragma unroll
        for (int t = 0; t < 8; t++) {
            int id = tid + t*256;
            int c = id & 127, j0 = (id >> 7) * 4;
            float4 v;
            v.x = gp[(size_t)(kb + j0 + 0)*stride + c];
            v.y = gp[(size_t)(kb + j0 + 1)*stride + c];
            v.z = gp[(size_t)(kb + j0 + 2)*stride + c];
            v.w = gp[(size_t)(kb + j0 + 3)*stride + c];
            *(float4*)&KV[c*68 + j0] = v;
        }

        // online softmax (4 threads/row), exp written back tf32-rounded
        float mx = -1e30f;
#pragma unroll
        for (int jj = 0; jj < 16; jj++)
            mx = fmaxf(mx, Ps[grow*68 + jj*4 + slane]);
        mx = fmaxf(mx, __shfl_xor_sync(0xffffffffu, mx, 1));
        mx = fmaxf(mx, __shfl_xor_sync(0xffffffffu, mx, 2));
        float m_new = fmaxf(m_run, mx);
        float alpha = __expf(m_run - m_new);
        float ssum = 0.f;
#pragma unroll
        for (int jj = 0; jj < 16; jj++) {
            int idx = grow*68 + jj*4 + slane;
            float e = tf32r(__expf(Ps[idx] - m_new));
            Ps[idx] = e;
            ssum += e;
        }
        ssum += __shfl_xor_sync(0xffffffffu, ssum, 1);
        ssum += __shfl_xor_sync(0xffffffffu, ssum, 2);
        l_run = l_run * alpha + ssum;
        m_run = m_new;
        if (slane == 0) red_alpha[grow] = alpha;
        __syncthreads();   // V, exp(S), alpha visible

        // O = O*alpha + P V (warp tile 16x64, 8 k8 steps)
        {
            float al0 = red_alpha[wm + frow];
            float al1 = red_alpha[wm + 8 + frow];
#pragma unroll
            for (int nt = 0; nt < 8; nt++) {
                o[nt][0] *= al0; o[nt][1] *= al0;
                o[nt][2] *= al1; o[nt][3] *= al1;
            }
        }
#pragma unroll
        for (int s = 0; s < 8; s++) {
            uint32_t a[4];
            ldm4(a, pa_base + s*32);
#pragma unroll
            for (int ntp = 0; ntp < 4; ntp++) {
                uint32_t b[4];
                ldm4(b, pb_base[ntp] + s*32);
                mma_tf32(o[ntp*2 + 0], a, &b[0]);
                mma_tf32(o[ntp*2 + 1], a, &b[2]);
            }
        }
    }

    if (slane == 0) red_l[grow] = l_run;
    __syncthreads();
    {
        float inv0 = 1.f / red_l[wm + frow];
        float inv1 = 1.f / red_l[wm + 8 + frow];
        int r0 = q0 + wm + frow;
#pragma unroll
        for (int nt = 0; nt < 8; nt++) {
            int cb = wnp + nt*8 + fcol2;
            *(float2*)&outp[(size_t)r0*stride + cb] =
                make_float2(tf32r(o[nt][0]*inv0), tf32r(o[nt][1]*inv0));
            *(float2*)&outp[(size_t)(r0 + 8)*stride + cb] =
                make_float2(tf32r(o[nt][2]*inv1), tf32r(o[nt][3]*inv1));
        }
    }
}

// ---------------- launch ----------------
extern "C" void kernel_launch(void* const* d_in, const int* in_sizes, int n_in,
                              void* d_out, int out_size) {
    const float* f  = (const float*)d_in[0];
    const float* W7 = (const float*)d_in[1];
    const float* m7 = (const float*)d_in[2];
    const float* v7 = (const float*)d_in[3];
    const float* b7 = (const float*)d_in[4];
    const float* Wa = (const float*)d_in[5];
    const float* ma = (const float*)d_in[6];
    const float* va = (const float*)d_in[7];
    const float* ba = (const float*)d_in[8];
    float* out = (float*)d_out;

    prep_kernel<<<64, 256>>>(W7, m7, v7, b7, Wa, ma, va, ba);

    transpose_in<<<dim3(HWD/32, CDIM/32, NB), dim3(32, 8)>>>(f);

    gemm_kernel<0><<<dim3(5, PTOT/128), 256>>>(nullptr);

    int smem_bytes = (8448 + 8704 + 4352 + 128) * 4;   // 86528
    cudaFuncSetAttribute(attn_kernel, cudaFuncAttributeMaxDynamicSharedMemorySize, smem_bytes);
    attn_kernel<<<dim3(LROW/64, NROWS, 2), 256, smem_bytes>>>();

    gemm_kernel<1><<<dim3(PTOT/128, 2), 256>>>(nullptr);

    gemm_kernel<2><<<dim3(PTOT/128, 1), 256>>>(out);
}

// round 12
// speedup vs baseline: 1.4787x; 1.4260x over previous
#include <cuda_runtime.h>
#include <cuda_fp16.h>
#include <math.h>
#include <cstdint>

#define NB 8
#define CDIM 128
#define HH 192
#define WW 192
#define HWD (HH*WW)          // 36864
#define PTOT (NB*HWD)        // 294912
#define LROW 192
#define NROWS (NB*HH)        // 1536
#define BN_EPS 1e-5f

// ---------------- cp.async / ldmatrix / mma helpers (family-portable) ----------------
__device__ __forceinline__ void cpa16(uint32_t s, const void* g) {
    asm volatile("cp.async.ca.shared.global [%0], [%1], 16;" :: "r"(s), "l"(g));
}
#define CP_COMMIT() asm volatile("cp.async.commit_group;" ::: "memory")
#define CP_WAIT0()  asm volatile("cp.async.wait_group 0;" ::: "memory")
#define CP_WAIT1()  asm volatile("cp.async.wait_group 1;" ::: "memory")

__device__ __forceinline__ void ldm4(uint32_t* r, uint32_t addr) {
    asm volatile("ldmatrix.sync.aligned.m8n8.x4.shared.b16 {%0,%1,%2,%3}, [%4];"
                 : "=r"(r[0]), "=r"(r[1]), "=r"(r[2]), "=r"(r[3]) : "r"(addr));
}
__device__ __forceinline__ void ldm4t(uint32_t* r, uint32_t addr) {
    asm volatile("ldmatrix.sync.aligned.m8n8.x4.trans.shared.b16 {%0,%1,%2,%3}, [%4];"
                 : "=r"(r[0]), "=r"(r[1]), "=r"(r[2]), "=r"(r[3]) : "r"(addr));
}
__device__ __forceinline__ void mma_f16(float* d, const uint32_t* a, uint32_t b0, uint32_t b1) {
    asm volatile(
        "mma.sync.aligned.m16n8k16.row.col.f32.f16.f16.f32 "
        "{%0,%1,%2,%3}, {%4,%5,%6,%7}, {%8,%9}, {%0,%1,%2,%3};"
        : "+f"(d[0]), "+f"(d[1]), "+f"(d[2]), "+f"(d[3])
        : "r"(a[0]), "r"(a[1]), "r"(a[2]), "r"(a[3]), "r"(b0), "r"(b1));
}

// ---------------- device scratch ----------------
__device__ __half g_th [PTOT*CDIM];   // theta (fp16), later u (fp16)
__device__ __half g_ph [PTOT*CDIM];   // phi,   later v
__device__ __half g_g  [PTOT*CDIM];   // g
__device__ __half g_ah [PTOT*CDIM];   // f_common NHWC fp16; attn-h out after
__device__ __half g_av [PTOT*CDIM];
__device__ float  g_sch[PTOT*CDIM];
__device__ float  g_scv[PTOT*CDIM];

__device__ __half g_WtA[5*CDIM*CDIM]; // [mat][d][k]
__device__ float  g_biasA[5*CDIM];
__device__ __half g_Wt3[CDIM*CDIM];
__device__ float  g_b3[CDIM];
__device__ __half g_Wt5[CDIM*CDIM];
__device__ float  g_b5[CDIM];
__device__ __half g_WtF[CDIM*2*CDIM]; // [d][256]
__device__ float  g_ba[CDIM];

// ---------------- BN folding prep (fp16 weights) ----------------
__global__ void prep_kernel(const float* __restrict__ W7, const float* __restrict__ m7,
                            const float* __restrict__ v7, const float* __restrict__ b7,
                            const float* __restrict__ Wa, const float* __restrict__ ma,
                            const float* __restrict__ va, const float* __restrict__ ba) {
    int t = blockIdx.x * blockDim.x + threadIdx.x;
    int stride = gridDim.x * blockDim.x;
    const int mats[5] = {0, 1, 2, 4, 6};
    for (int idx = t; idx < 5*128*128; idx += stride) {
        int m = idx >> 14, r = idx & 16383, d = r >> 7, k = r & 127;
        int mm = mats[m];
        float rs = rsqrtf(v7[mm*128 + d] + BN_EPS);
        g_WtA[idx] = __float2half_rn(W7[(mm*128 + k)*128 + d] * rs);
        if (k == 0) g_biasA[m*128 + d] = b7[mm*128 + d] - m7[mm*128 + d]*rs;
    }
    for (int idx = t; idx < 128*128; idx += stride) {
        int d = idx >> 7, k = idx & 127;
        float rs3 = rsqrtf(v7[3*128 + d] + BN_EPS);
        float rs5 = rsqrtf(v7[5*128 + d] + BN_EPS);
        g_Wt3[idx] = __float2half_rn(W7[(3*128 + k)*128 + d] * rs3);
        g_Wt5[idx] = __float2half_rn(W7[(5*128 + k)*128 + d] * rs5);
        if (k == 0) {
            g_b3[d] = b7[3*128 + d] - m7[3*128 + d]*rs3;
            g_b5[d] = b7[5*128 + d] - m7[5*128 + d]*rs5;
        }
    }
    for (int idx = t; idx < 128*256; idx += stride) {
        int d = idx >> 8, kk = idx & 255;
        float rs = rsqrtf(va[d] + BN_EPS);
        g_WtF[idx] = __float2half_rn(Wa[kk*128 + d] * rs);
        if (kk == 0) g_ba[d] = ba[d] - ma[d]*rs;
    }
}

// ---------------- NCHW -> NHWC input transpose (into g_ah, fp16) ----------------
__global__ void transpose_in(const float* __restrict__ f) {
    __shared__ float tile[32][33];
    int n = blockIdx.z, hw0 = blockIdx.x * 32, c0 = blockIdx.y * 32;
    int tx = threadIdx.x, ty = threadIdx.y;
    const float* src = f + (size_t)n*CDIM*HWD;
#pragma unroll
    for (int i = 0; i < 32; i += 8)
        tile[ty + i][tx] = src[(size_t)(c0 + ty + i)*HWD + hw0 + tx];
    __syncthreads();
    __half* dst = g_ah + (size_t)n*HWD*CDIM;
#pragma unroll
    for (int i = 0; i < 32; i += 8)
        dst[(size_t)(hw0 + ty + i)*CDIM + c0 + tx] = __float2half_rn(tile[tx][ty + i]);
}

// ---------------- fp16 tensor-core GEMM (m16n8k16), plane-layout K32 slices ----------------
// MODE 0: grid (5, pixblocks). MODE 1: grid (pixblocks, 2). MODE 2: grid (pixblocks, 1), K=256.
template<int MODE>
__global__ __launch_bounds__(256, 2) void gemm_kernel(float* __restrict__ out) {
    __shared__ __align__(16) char smg[33024];    // [2][8KB] A | [2][8KB] B ; MODE2 epilogue reuses as 64x129 fp32
    const int tid = threadIdx.x;
    const int wid = tid >> 5, lane = tid & 31;
    int p0, y;
    if (MODE == 0) { y = blockIdx.x; p0 = blockIdx.y * 128; }
    else           { y = blockIdx.y; p0 = blockIdx.x * 128; }
    const int wm = (wid & 3) * 32;
    const int wn = (wid >> 2) * 64;

    const int KT = (MODE == 2) ? 8 : 4;          // K32 slices
    const __half* Abase0; const __half* Bp; int ldkB;
    if (MODE == 0)      { Abase0 = g_ah;            Bp = g_WtA + y*16384;   ldkB = 128; }
    else if (MODE == 1) { Abase0 = y ? g_av : g_ah; Bp = y ? g_Wt5 : g_Wt3; ldkB = 128; }
    else                { Abase0 = g_th;            Bp = g_WtF;             ldkB = 256; }

    uint32_t sa_u = (uint32_t)__cvta_generic_to_shared(smg);
    uint32_t sb_u = sa_u + 16384;

    const int l15 = lane & 15, lg = lane >> 4;
    uint32_t aoff[2], boff[4];
#pragma unroll
    for (int mt = 0; mt < 2; mt++)
        aoff[mt] = (uint32_t)(lg*2048 + (wm + mt*16 + l15)*16);
#pragma unroll
    for (int ntp = 0; ntp < 4; ntp++)
        boff[ntp] = (uint32_t)(lg*2048 + (wn + ntp*16 + l15)*16);

    float acc[2][8][4];
#pragma unroll
    for (int mt = 0; mt < 2; mt++)
#pragma unroll
        for (int nt = 0; nt < 8; nt++)
#pragma unroll
            for (int q = 0; q < 4; q++) acc[mt][nt][q] = 0.f;

    auto load_tile = [&](int t, int buf) {
        int k0 = t * 32;
        const __half* asrc;
        if (MODE == 2) asrc = ((t < 4) ? g_th : g_ph) + (size_t)p0*128 + (k0 & 127);
        else           asrc = Abase0 + (size_t)p0*128 + k0;
        uint32_t sab = sa_u + (uint32_t)buf*8192;
        uint32_t sbb = sb_u + (uint32_t)buf*8192;
#pragma unroll
        for (int i = 0; i < 2; i++) {
            int id = tid + i*256;                // 512 granules
            int o = id & 3, r = id >> 2;
            cpa16(sab + (uint32_t)(o*2048 + r*16), asrc + (size_t)r*128 + o*8);
        }
        const __half* bsrc = Bp + k0;
#pragma unroll
        for (int i = 0; i < 2; i++) {
            int id = tid + i*256;
            int o = id & 3, n = id >> 2;
            cpa16(sbb + (uint32_t)(o*2048 + n*16), bsrc + (size_t)n*ldkB + o*8);
        }
        CP_COMMIT();
    };

    load_tile(0, 0);
    int buf = 0;
    for (int t = 0; t < KT; t++) {
        CP_WAIT0();
        __syncthreads();
        if (t + 1 < KT) load_tile(t + 1, buf ^ 1);

        uint32_t sab = sa_u + (uint32_t)buf*8192;
        uint32_t sbb = sb_u + (uint32_t)buf*8192;
#pragma unroll
        for (int s = 0; s < 2; s++) {
            uint32_t a[2][4], b[4][4];
#pragma unroll
            for (int mt = 0; mt < 2; mt++)
                ldm4(a[mt], sab + (uint32_t)s*4096 + aoff[mt]);
#pragma unroll
            for (int ntp = 0; ntp < 4; ntp++)
                ldm4(b[ntp], sbb + (uint32_t)s*4096 + boff[ntp]);
#pragma unroll
            for (int mt = 0; mt < 2; mt++)
#pragma unroll
                for (int ntp = 0; ntp < 4; ntp++) {
                    mma_f16(acc[mt][ntp*2 + 0], a[mt], b[ntp][0], b[ntp][2]);
                    mma_f16(acc[mt][ntp*2 + 1], a[mt], b[ntp][1], b[ntp][3]);
                }
        }
        __syncthreads();
        buf ^= 1;
    }

    if (MODE == 2) {
        const float* biasp = g_ba;
        float* SP = (float*)smg;                 // 64*129*4 = 33024 B
        const int n_img = p0 / HWD, hw0 = p0 % HWD;
        float* obase = out + (size_t)n_img*CDIM*HWD + hw0;
#pragma unroll
        for (int ch = 0; ch < 2; ch++) {
            if ((wid >> 2) == ch) {
#pragma unroll
                for (int nt = 0; nt < 8; nt++) {
                    int cb = nt*8 + (lane & 3)*2;
                    float b0 = biasp[ch*64 + cb], b1 = biasp[ch*64 + cb + 1];
#pragma unroll
                    for (int mt = 0; mt < 2; mt++)
#pragma unroll
                        for (int half = 0; half < 2; half++) {
                            int row = wm + (lane >> 2) + mt*16 + half*8;
                            SP[cb*129 + row]     = fmaxf(acc[mt][nt][half*2 + 0] + b0, 0.f);
                            SP[(cb+1)*129 + row] = fmaxf(acc[mt][nt][half*2 + 1] + b1, 0.f);
                        }
                }
            }
            __syncthreads();
#pragma unroll
            for (int t2 = 0; t2 < 32; t2++) {
                int id = tid + t2*256;
                int c = id >> 7, pix = id & 127;
                obase[(size_t)(ch*64 + c)*HWD + pix] = SP[c*129 + pix];
            }
            __syncthreads();
        }
        return;
    }

    // epilogues for MODE 0/1
    const float* biasp; const float* addp = nullptr;
    __half* houtp = nullptr; float* foutp = nullptr;
    if (MODE == 0) {
        biasp = g_biasA + y*128;
        if (y < 3) houtp = (y==0) ? g_th : (y==1) ? g_ph : g_g;
        else       foutp = (y==3) ? g_sch : g_scv;
    } else {
        houtp = y ? g_ph : g_th;
        biasp = y ? g_b5 : g_b3;
        addp  = y ? g_scv : g_sch;
    }

    const int rbase = p0 + wm + (lane >> 2);
#pragma unroll
    for (int nt = 0; nt < 8; nt++) {
        int cb = wn + nt*8 + (lane & 3)*2;
        float b0 = biasp[cb], b1 = biasp[cb + 1];
#pragma unroll
        for (int mt = 0; mt < 2; mt++) {
#pragma unroll
            for (int half = 0; half < 2; half++) {
                int row = rbase + mt*16 + half*8;
                size_t ro = (size_t)row*128 + cb;
                float v0 = acc[mt][nt][half*2 + 0] + b0;
                float v1 = acc[mt][nt][half*2 + 1] + b1;
                if (MODE == 1) {
                    float2 ad = *(const float2*)(addp + ro);
                    v0 += ad.x; v1 += ad.y;
                }
                if (MODE == 1 || y < 3) { v0 = fmaxf(v0, 0.f); v1 = fmaxf(v1, 0.f); }
                if (houtp) *(__half2*)(houtp + ro) = __floats2half2_rn(v0, v1);
                else       *(float2*)(foutp + ro) = make_float2(v0, v1);
            }
        }
    }
}

// ---------------- axial attention: FA-style on mma.sync fp16 ----------------
// smem bytes: Q [64][128]h swz @0 | K @16384 | V @32768 | Ps [64][64]h swz @49152 |
//             pmax fp32[2][64] @57344 | psum fp32[2][64] @57856 ; total 58368
__global__ __launch_bounds__(256, 2) void attn_kernel() {
    extern __shared__ char smc[];
    uint32_t s_u = (uint32_t)__cvta_generic_to_shared(smc);
    uint32_t q_u = s_u, k_u = s_u + 16384, v_u = s_u + 32768, p_u = s_u + 49152;
    float* pmax = (float*)(smc + 57344);
    float* psum = (float*)(smc + 57856);

    const int tid = threadIdx.x;
    const int wid = tid >> 5, lane = tid & 31;
    const int q0 = blockIdx.x * 64;
    const int brow_idx = blockIdx.y;
    const int dir = blockIdx.z;

    size_t base; int stride;
    if (dir == 0) { base = (size_t)brow_idx * LROW * CDIM; stride = CDIM; }
    else {
        int n = brow_idx / WW, w = brow_idx % WW;
        base = (size_t)n*HH*WW*CDIM + (size_t)w*CDIM;
        stride = WW*CDIM;
    }
    const __half* thp = g_th + base;
    const __half* php = g_ph + base;
    const __half* gp  = g_g  + base;
    __half* outp = (dir == 0 ? g_ah : g_av) + base;

    // Q fill (once): swizzled 256B rows
#pragma unroll
    for (int t = 0; t < 4; t++) {
        int id = tid + t*256;
        int i = id >> 4, g = id & 15;
        cpa16(q_u + (uint32_t)(i*256 + ((g ^ (i & 7)) << 4)),
              thp + (size_t)(q0 + i)*stride + g*8);
    }
    CP_COMMIT();

    const int l15 = lane & 15, lg = lane >> 4;
    const int frow = lane >> 2, fcol2 = (lane & 3)*2;
    const int wm = (wid & 3) * 16;
    const int wnsI = wid >> 2;                 // 0/1
    const int wns = wnsI * 32, wnp = wnsI * 64;

    const int rowA = wm + l15;                 // Q / Ps fragment rows
    const uint32_t qbase = q_u + rowA*256;
    const uint32_t pbase = p_u + rowA*128;
    const int xA = rowA & 7;
    const int rowK0 = wns + l15, rowK1 = wns + 16 + l15;
    const uint32_t kb0 = k_u + rowK0*256, kb1 = k_u + rowK1*256;
    const int xK0 = rowK0 & 7, xK1 = rowK1 & 7;
    const int jrow = (lane & 7) + (lane & 8);  // V (.trans) rows
    const uint32_t vbase = v_u + jrow*256;
    const int jx = lane & 7;
    uint32_t voff[4];
#pragma unroll
    for (int ntp = 0; ntp < 4; ntp++)
        voff[ntp] = (uint32_t)((((wnp >> 3) + ntp*2 + lg) ^ jx) << 4);

    float o[8][4];
#pragma unroll
    for (int nt = 0; nt < 8; nt++)
#pragma unroll
        for (int q = 0; q < 4; q++) o[nt][q] = 0.f;
    float m0 = -1e30f, m1 = -1e30f, l0 = 0.f, l1 = 0.f;
    const float scale = 0.08838834764831845f;  // 1/sqrt(128)

    for (int kb = 0; kb < LROW; kb += 64) {
        __syncthreads();   // guards K/V/Ps reuse from prior chunk
        // K fill
#pragma unroll
        for (int t = 0; t < 4; t++) {
            int id = tid + t*256;
            int j = id >> 4, g = id & 15;
            cpa16(k_u + (uint32_t)(j*256 + ((g ^ (j & 7)) << 4)),
                  php + (size_t)(kb + j)*stride + g*8);
        }
        CP_COMMIT();
        // V fill (overlaps S-phase)
#pragma unroll
        for (int t = 0; t < 4; t++) {
            int id = tid + t*256;
            int j = id >> 4, g = id & 15;
            cpa16(v_u + (uint32_t)(j*256 + ((g ^ (j & 7)) << 4)),
                  gp + (size_t)(kb + j)*stride + g*8);
        }
        CP_COMMIT();
        CP_WAIT1();        // K (and Q on first chunk) ready; V still in flight
        __syncthreads();

        // S = Q K^T  (warp tile 16x32, 8 k16 steps)
        float sacc[4][4];
#pragma unroll
        for (int nt = 0; nt < 4; nt++)
#pragma unroll
            for (int q = 0; q < 4; q++) sacc[nt][q] = 0.f;
#pragma unroll
        for (int s = 0; s < 8; s++) {
            uint32_t a[4], b0[4], b1[4];
            ldm4(a,  qbase + (uint32_t)(((2*s + lg) ^ xA)  << 4));
            ldm4(b0, kb0   + (uint32_t)(((2*s + lg) ^ xK0) << 4));
            ldm4(b1, kb1   + (uint32_t)(((2*s + lg) ^ xK1) << 4));
            mma_f16(sacc[0], a, b0[0], b0[2]);
            mma_f16(sacc[1], a, b0[1], b0[3]);
            mma_f16(sacc[2], a, b1[0], b1[2]);
            mma_f16(sacc[3], a, b1[1], b1[3]);
        }

        // softmax stage 1: per-warp partial row max over its 32 j
        float r0 = -1e30f, r1 = -1e30f;
#pragma unroll
        for (int nt = 0; nt < 4; nt++) {
            sacc[nt][0] *= scale; sacc[nt][1] *= scale;
            sacc[nt][2] *= scale; sacc[nt][3] *= scale;
            r0 = fmaxf(r0, fmaxf(sacc[nt][0], sacc[nt][1]));
            r1 = fmaxf(r1, fmaxf(sacc[nt][2], sacc[nt][3]));
        }
        r0 = fmaxf(r0, __shfl_xor_sync(0xffffffffu, r0, 1));
        r0 = fmaxf(r0, __shfl_xor_sync(0xffffffffu, r0, 2));
        r1 = fmaxf(r1, __shfl_xor_sync(0xffffffffu, r1, 1));
        r1 = fmaxf(r1, __shfl_xor_sync(0xffffffffu, r1, 2));
        if ((lane & 3) == 0) {
            pmax[wnsI*64 + wm + frow]     = r0;
            pmax[wnsI*64 + wm + 8 + frow] = r1;
        }
        __syncthreads();

        // softmax stage 2: combine, exp, write P (half2 frags), partial sums
        const int ro0 = wm + frow, ro1 = ro0 + 8;
        float mn0 = fmaxf(m0, fmaxf(pmax[ro0], pmax[64 + ro0]));
        float mn1 = fmaxf(m1, fmaxf(pmax[ro1], pmax[64 + ro1]));
        float al0 = __expf(m0 - mn0), al1 = __expf(m1 - mn1);
        float s0a = 0.f, s1a = 0.f;
#pragma unroll
        for (int nt = 0; nt < 4; nt++) {
            __half2 h01 = __floats2half2_rn(__expf(sacc[nt][0] - mn0), __expf(sacc[nt][1] - mn0));
            __half2 h23 = __floats2half2_rn(__expf(sacc[nt][2] - mn1), __expf(sacc[nt][3] - mn1));
            int jg = wnsI*4 + nt;
            *(__half2*)(smc + 49152 + ro0*128 + ((jg ^ (ro0 & 7)) << 4) + fcol2*2) = h01;
            *(__half2*)(smc + 49152 + ro1*128 + ((jg ^ (ro1 & 7)) << 4) + fcol2*2) = h23;
            float2 e01 = __half22float2(h01), e23 = __half22float2(h23);
            s0a += e01.x + e01.y; s1a += e23.x + e23.y;
        }
        s0a += __shfl_xor_sync(0xffffffffu, s0a, 1);
        s0a += __shfl_xor_sync(0xffffffffu, s0a, 2);
        s1a += __shfl_xor_sync(0xffffffffu, s1a, 1);
        s1a += __shfl_xor_sync(0xffffffffu, s1a, 2);
        if ((lane & 3) == 0) {
            psum[wnsI*64 + ro0] = s0a;
            psum[wnsI*64 + ro1] = s1a;
        }
        CP_WAIT0();        // V landed
        __syncthreads();   // Ps + psum + V visible

        l0 = l0*al0 + (psum[ro0] + psum[64 + ro0]);
        l1 = l1*al1 + (psum[ro1] + psum[64 + ro1]);
        m0 = mn0; m1 = mn1;
#pragma unroll
        for (int nt = 0; nt < 8; nt++) {
            o[nt][0] *= al0; o[nt][1] *= al0;
            o[nt][2] *= al1; o[nt][3] *= al1;
        }

        // O += P V  (warp tile 16x64, 4 k16 steps; V via ldmatrix.trans)
#pragma unroll
        for (int s = 0; s < 4; s++) {
            uint32_t pa[4];
            ldm4(pa, pbase + (uint32_t)(((2*s + lg) ^ xA) << 4));
#pragma unroll
            for (int ntp = 0; ntp < 4; ntp++) {
                uint32_t vb[4];
                ldm4t(vb, vbase + (uint32_t)s*4096 + voff[ntp]);
                mma_f16(o[ntp*2 + 0], pa, vb[0], vb[1]);
                mma_f16(o[ntp*2 + 1], pa, vb[2], vb[3]);
            }
        }
    }

    {
        float inv0 = 1.f / l0, inv1 = 1.f / l1;
        int r0w = q0 + wm + frow;
#pragma unroll
        for (int nt = 0; nt < 8; nt++) {
            int cb = wnp + nt*8 + fcol2;
            *(__half2*)(outp + (size_t)r0w*stride + cb) =
                __floats2half2_rn(o[nt][0]*inv0, o[nt][1]*inv0);
            *(__half2*)(outp + (size_t)(r0w + 8)*stride + cb) =
                __floats2half2_rn(o[nt][2]*inv1, o[nt][3]*inv1);
        }
    }
}

// ---------------- launch ----------------
extern "C" void kernel_launch(void* const* d_in, const int* in_sizes, int n_in,
                              void* d_out, int out_size) {
    const float* f  = (const float*)d_in[0];
    const float* W7 = (const float*)d_in[1];
    const float* m7 = (const float*)d_in[2];
    const float* v7 = (const float*)d_in[3];
    const float* b7 = (const float*)d_in[4];
    const float* Wa = (const float*)d_in[5];
    const float* ma = (const float*)d_in[6];
    const float* va = (const float*)d_in[7];
    const float* ba = (const float*)d_in[8];
    float* out = (float*)d_out;

    prep_kernel<<<64, 256>>>(W7, m7, v7, b7, Wa, ma, va, ba);

    transpose_in<<<dim3(HWD/32, CDIM/32, NB), dim3(32, 8)>>>(f);

    gemm_kernel<0><<<dim3(5, PTOT/128), 256>>>(nullptr);

    int smem_bytes = 58368;
    cudaFuncSetAttribute(attn_kernel, cudaFuncAttributeMaxDynamicSharedMemorySize, smem_bytes);
    attn_kernel<<<dim3(LROW/64, NROWS, 2), 256, smem_bytes>>>();

    gemm_kernel<1><<<dim3(PTOT/128, 2), 256>>>(nullptr);

    gemm_kernel<2><<<dim3(PTOT/128, 1), 256>>>(out);
}

// round 13
// speedup vs baseline: 1.6682x; 1.1282x over previous
#include <cuda_runtime.h>
#include <cuda_fp16.h>
#include <math.h>
#include <cstdint>

#define NB 8
#define CDIM 128
#define HH 192
#define WW 192
#define HWD (HH*WW)          // 36864
#define PTOT (NB*HWD)        // 294912
#define LROW 192
#define NROWS (NB*HH)        // 1536
#define BN_EPS 1e-5f

// ---------------- cp.async / ldmatrix / mma helpers (family-portable) ----------------
__device__ __forceinline__ void cpa16(uint32_t s, const void* g) {
    asm volatile("cp.async.ca.shared.global [%0], [%1], 16;" :: "r"(s), "l"(g));
}
#define CP_COMMIT() asm volatile("cp.async.commit_group;" ::: "memory")
#define CP_WAIT0()  asm volatile("cp.async.wait_group 0;" ::: "memory")
#define CP_WAIT1()  asm volatile("cp.async.wait_group 1;" ::: "memory")

__device__ __forceinline__ void ldm4(uint32_t* r, uint32_t addr) {
    asm volatile("ldmatrix.sync.aligned.m8n8.x4.shared.b16 {%0,%1,%2,%3}, [%4];"
                 : "=r"(r[0]), "=r"(r[1]), "=r"(r[2]), "=r"(r[3]) : "r"(addr));
}
__device__ __forceinline__ void ldm4t(uint32_t* r, uint32_t addr) {
    asm volatile("ldmatrix.sync.aligned.m8n8.x4.trans.shared.b16 {%0,%1,%2,%3}, [%4];"
                 : "=r"(r[0]), "=r"(r[1]), "=r"(r[2]), "=r"(r[3]) : "r"(addr));
}
__device__ __forceinline__ void mma_f16(float* d, const uint32_t* a, uint32_t b0, uint32_t b1) {
    asm volatile(
        "mma.sync.aligned.m16n8k16.row.col.f32.f16.f16.f32 "
        "{%0,%1,%2,%3}, {%4,%5,%6,%7}, {%8,%9}, {%0,%1,%2,%3};"
        : "+f"(d[0]), "+f"(d[1]), "+f"(d[2]), "+f"(d[3])
        : "r"(a[0]), "r"(a[1]), "r"(a[2]), "r"(a[3]), "r"(b0), "r"(b1));
}

// ---------------- device scratch ----------------
__device__ __half g_th [PTOT*CDIM];   // theta (fp16)
__device__ __half g_ph [PTOT*CDIM];   // phi
__device__ __half g_g  [PTOT*CDIM];   // g
__device__ __half g_ah [PTOT*CDIM];   // f_common NHWC fp16; attn-h out after
__device__ __half g_av [PTOT*CDIM];
__device__ __half g_sch[PTOT*CDIM];   // shortcuts now fp16
__device__ __half g_scv[PTOT*CDIM];

__device__ __half g_WtA[5*CDIM*CDIM]; // [mat][d][k]
__device__ float  g_biasA[5*CDIM];
__device__ __half g_Wt3[CDIM*CDIM];
__device__ float  g_b3[CDIM];
__device__ __half g_Wt5[CDIM*CDIM];
__device__ float  g_b5[CDIM];
__device__ __half g_WtF[CDIM*2*CDIM]; // [d][256]
__device__ float  g_ba[CDIM];

// ---------------- BN folding prep (fp16 weights) ----------------
__global__ void prep_kernel(const float* __restrict__ W7, const float* __restrict__ m7,
                            const float* __restrict__ v7, const float* __restrict__ b7,
                            const float* __restrict__ Wa, const float* __restrict__ ma,
                            const float* __restrict__ va, const float* __restrict__ ba) {
    int t = blockIdx.x * blockDim.x + threadIdx.x;
    int stride = gridDim.x * blockDim.x;
    const int mats[5] = {0, 1, 2, 4, 6};
    for (int idx = t; idx < 5*128*128; idx += stride) {
        int m = idx >> 14, r = idx & 16383, d = r >> 7, k = r & 127;
        int mm = mats[m];
        float rs = rsqrtf(v7[mm*128 + d] + BN_EPS);
        g_WtA[idx] = __float2half_rn(W7[(mm*128 + k)*128 + d] * rs);
        if (k == 0) g_biasA[m*128 + d] = b7[mm*128 + d] - m7[mm*128 + d]*rs;
    }
    for (int idx = t; idx < 128*128; idx += stride) {
        int d = idx >> 7, k = idx & 127;
        float rs3 = rsqrtf(v7[3*128 + d] + BN_EPS);
        float rs5 = rsqrtf(v7[5*128 + d] + BN_EPS);
        g_Wt3[idx] = __float2half_rn(W7[(3*128 + k)*128 + d] * rs3);
        g_Wt5[idx] = __float2half_rn(W7[(5*128 + k)*128 + d] * rs5);
        if (k == 0) {
            g_b3[d] = b7[3*128 + d] - m7[3*128 + d]*rs3;
            g_b5[d] = b7[5*128 + d] - m7[5*128 + d]*rs5;
        }
    }
    for (int idx = t; idx < 128*256; idx += stride) {
        int d = idx >> 8, kk = idx & 255;
        float rs = rsqrtf(va[d] + BN_EPS);
        g_WtF[idx] = __float2half_rn(Wa[kk*128 + d] * rs);
        if (kk == 0) g_ba[d] = ba[d] - ma[d]*rs;
    }
}

// ---------------- NCHW -> NHWC input transpose (into g_ah, fp16) ----------------
__global__ void transpose_in(const float* __restrict__ f) {
    __shared__ float tile[32][33];
    int n = blockIdx.z, hw0 = blockIdx.x * 32, c0 = blockIdx.y * 32;
    int tx = threadIdx.x, ty = threadIdx.y;
    const float* src = f + (size_t)n*CDIM*HWD;
#pragma unroll
    for (int i = 0; i < 32; i += 8)
        tile[ty + i][tx] = src[(size_t)(c0 + ty + i)*HWD + hw0 + tx];
    __syncthreads();
    __half* dst = g_ah + (size_t)n*HWD*CDIM;
#pragma unroll
    for (int i = 0; i < 32; i += 8)
        dst[(size_t)(hw0 + ty + i)*CDIM + c0 + tx] = __float2half_rn(tile[tx][ty + i]);
}

// ---------------- stage A GEMM: f x 5 weight mats -> th/ph/g/sch/scv (all fp16) ----------------
__global__ __launch_bounds__(256, 2) void gemm0_kernel() {
    __shared__ __align__(16) char smg[32768];    // [2][8KB] A | [2][8KB] B
    const int tid = threadIdx.x;
    const int wid = tid >> 5, lane = tid & 31;
    const int y = blockIdx.x;
    const int p0 = blockIdx.y * 128;
    const int wm = (wid & 3) * 32;
    const int wn = (wid >> 2) * 64;

    const __half* Abase0 = g_ah;
    const __half* Bp = g_WtA + y*16384;

    uint32_t sa_u = (uint32_t)__cvta_generic_to_shared(smg);
    uint32_t sb_u = sa_u + 16384;

    const int l15 = lane & 15, lg = lane >> 4;
    uint32_t aoff[2], boff[4];
#pragma unroll
    for (int mt = 0; mt < 2; mt++)
        aoff[mt] = (uint32_t)(lg*2048 + (wm + mt*16 + l15)*16);
#pragma unroll
    for (int ntp = 0; ntp < 4; ntp++)
        boff[ntp] = (uint32_t)(lg*2048 + (wn + ntp*16 + l15)*16);

    float acc[2][8][4];
#pragma unroll
    for (int mt = 0; mt < 2; mt++)
#pragma unroll
        for (int nt = 0; nt < 8; nt++)
#pragma unroll
            for (int q = 0; q < 4; q++) acc[mt][nt][q] = 0.f;

    auto load_tile = [&](int t, int buf) {
        int k0 = t * 32;
        const __half* asrc = Abase0 + (size_t)p0*128 + k0;
        uint32_t sab = sa_u + (uint32_t)buf*8192;
        uint32_t sbb = sb_u + (uint32_t)buf*8192;
#pragma unroll
        for (int i = 0; i < 2; i++) {
            int id = tid + i*256;
            int o = id & 3, r = id >> 2;
            cpa16(sab + (uint32_t)(o*2048 + r*16), asrc + (size_t)r*128 + o*8);
        }
        const __half* bsrc = Bp + k0;
#pragma unroll
        for (int i = 0; i < 2; i++) {
            int id = tid + i*256;
            int o = id & 3, n = id >> 2;
            cpa16(sbb + (uint32_t)(o*2048 + n*16), bsrc + (size_t)n*128 + o*8);
        }
        CP_COMMIT();
    };

    load_tile(0, 0);
    int buf = 0;
    for (int t = 0; t < 4; t++) {
        CP_WAIT0();
        __syncthreads();
        if (t + 1 < 4) load_tile(t + 1, buf ^ 1);

        uint32_t sab = sa_u + (uint32_t)buf*8192;
        uint32_t sbb = sb_u + (uint32_t)buf*8192;
#pragma unroll
        for (int s = 0; s < 2; s++) {
            uint32_t a[2][4], b[4][4];
#pragma unroll
            for (int mt = 0; mt < 2; mt++)
                ldm4(a[mt], sab + (uint32_t)s*4096 + aoff[mt]);
#pragma unroll
            for (int ntp = 0; ntp < 4; ntp++)
                ldm4(b[ntp], sbb + (uint32_t)s*4096 + boff[ntp]);
#pragma unroll
            for (int mt = 0; mt < 2; mt++)
#pragma unroll
                for (int ntp = 0; ntp < 4; ntp++) {
                    mma_f16(acc[mt][ntp*2 + 0], a[mt], b[ntp][0], b[ntp][2]);
                    mma_f16(acc[mt][ntp*2 + 1], a[mt], b[ntp][1], b[ntp][3]);
                }
        }
        __syncthreads();
        buf ^= 1;
    }

    __half* houtp = (y==0) ? g_th : (y==1) ? g_ph : (y==2) ? g_g : (y==3) ? g_sch : g_scv;
    const float* biasp = g_biasA + y*128;
    const bool relu = (y < 3);

    const int rbase = p0 + wm + (lane >> 2);
#pragma unroll
    for (int nt = 0; nt < 8; nt++) {
        int cb = wn + nt*8 + (lane & 3)*2;
        float b0 = biasp[cb], b1 = biasp[cb + 1];
#pragma unroll
        for (int mt = 0; mt < 2; mt++) {
#pragma unroll
            for (int half = 0; half < 2; half++) {
                int row = rbase + mt*16 + half*8;
                size_t ro = (size_t)row*128 + cb;
                float v0 = acc[mt][nt][half*2 + 0] + b0;
                float v1 = acc[mt][nt][half*2 + 1] + b1;
                if (relu) { v0 = fmaxf(v0, 0.f); v1 = fmaxf(v1, 0.f); }
                *(__half2*)(houtp + ro) = __floats2half2_rn(v0, v1);
            }
        }
    }
}

// ---------------- fused C-stage: u/v (with shortcut+relu) in smem, then final conv -> NCHW ----------------
// dyn smem: staging 32KB @0 (A dbl [0,16K), B dbl [16K,32K)) | U 32KB @32768 | V 32KB @65536
// U/V stored in plane-slice layout so phase-2 ldmatrix uses the standard aoff pattern.
__global__ __launch_bounds__(256, 2) void fusedc_kernel(float* __restrict__ out) {
    extern __shared__ __align__(16) char smf[];
    const int tid = threadIdx.x;
    const int wid = tid >> 5, lane = tid & 31;
    const int p0 = blockIdx.x * 128;
    const int wm = (wid & 3) * 32;
    const int wn = (wid >> 2) * 64;

    uint32_t s_u = (uint32_t)__cvta_generic_to_shared(smf);
    uint32_t sa_u = s_u, sb_u = s_u + 16384;
    uint32_t uv_u = s_u + 32768;

    const int l15 = lane & 15, lg = lane >> 4;
    uint32_t aoff[2], boff[4];
#pragma unroll
    for (int mt = 0; mt < 2; mt++)
        aoff[mt] = (uint32_t)(lg*2048 + (wm + mt*16 + l15)*16);
#pragma unroll
    for (int ntp = 0; ntp < 4; ntp++)
        boff[ntp] = (uint32_t)(lg*2048 + (wn + ntp*16 + l15)*16);

    float acc[2][8][4];

    // ---- Phase 1: u (y=0) and v (y=1) into U/V smem ----
#pragma unroll 1
    for (int y = 0; y < 2; y++) {
        const __half* Abase0 = y ? g_av : g_ah;
        const __half* Bp = y ? g_Wt5 : g_Wt3;
        const __half* scp = (y ? g_scv : g_sch) + (size_t)p0*128;
        const float* biasp = y ? g_b5 : g_b3;
        char* UV = smf + 32768 + y*32768;

#pragma unroll
        for (int mt = 0; mt < 2; mt++)
#pragma unroll
            for (int nt = 0; nt < 8; nt++)
#pragma unroll
                for (int q = 0; q < 4; q++) acc[mt][nt][q] = 0.f;

        auto load_tile = [&](int t, int buf) {
            int k0 = t * 32;
            const __half* asrc = Abase0 + (size_t)p0*128 + k0;
            uint32_t sab = sa_u + (uint32_t)buf*8192;
            uint32_t sbb = sb_u + (uint32_t)buf*8192;
#pragma unroll
            for (int i = 0; i < 2; i++) {
                int id = tid + i*256;
                int o = id & 3, r = id >> 2;
                cpa16(sab + (uint32_t)(o*2048 + r*16), asrc + (size_t)r*128 + o*8);
            }
            const __half* bsrc = Bp + k0;
#pragma unroll
            for (int i = 0; i < 2; i++) {
                int id = tid + i*256;
                int o = id & 3, n = id >> 2;
                cpa16(sbb + (uint32_t)(o*2048 + n*16), bsrc + (size_t)n*128 + o*8);
            }
            CP_COMMIT();
        };

        load_tile(0, 0);
        int buf = 0;
        for (int t = 0; t < 4; t++) {
            CP_WAIT0();
            __syncthreads();
            if (t + 1 < 4) load_tile(t + 1, buf ^ 1);

            uint32_t sab = sa_u + (uint32_t)buf*8192;
            uint32_t sbb = sb_u + (uint32_t)buf*8192;
#pragma unroll
            for (int s = 0; s < 2; s++) {
                uint32_t a[2][4], b[4][4];
#pragma unroll
                for (int mt = 0; mt < 2; mt++)
                    ldm4(a[mt], sab + (uint32_t)s*4096 + aoff[mt]);
#pragma unroll
                for (int ntp = 0; ntp < 4; ntp++)
                    ldm4(b[ntp], sbb + (uint32_t)s*4096 + boff[ntp]);
#pragma unroll
                for (int mt = 0; mt < 2; mt++)
#pragma unroll
                    for (int ntp = 0; ntp < 4; ntp++) {
                        mma_f16(acc[mt][ntp*2 + 0], a[mt], b[ntp][0], b[ntp][2]);
                        mma_f16(acc[mt][ntp*2 + 1], a[mt], b[ntp][1], b[ntp][3]);
                    }
            }
            __syncthreads();
            buf ^= 1;
        }

        // epilogue: +shortcut(fp16) +relu -> UV plane-slice layout
#pragma unroll
        for (int nt = 0; nt < 8; nt++) {
            int cb = wn + nt*8 + (lane & 3)*2;     // k index (even)
            float b0 = biasp[cb], b1 = biasp[cb + 1];
            uint32_t pl = (uint32_t)((cb >> 5)*8192 + ((cb >> 3) & 3)*2048 + (cb & 7)*2);
#pragma unroll
            for (int mt = 0; mt < 2; mt++) {
#pragma unroll
                for (int half = 0; half < 2; half++) {
                    int row = wm + (lane >> 2) + mt*16 + half*8;   // local 0..127
                    float2 sc = __half22float2(*(const __half2*)(scp + (size_t)row*128 + cb));
                    float v0 = fmaxf(acc[mt][nt][half*2 + 0] + b0 + sc.x, 0.f);
                    float v1 = fmaxf(acc[mt][nt][half*2 + 1] + b1 + sc.y, 0.f);
                    *(__half2*)(UV + pl + row*16) = __floats2half2_rn(v0, v1);
                }
            }
        }
        __syncthreads();
    }

    // ---- Phase 2: out = relu([u v] * WtF + ba), A from smem, direct NCHW write ----
#pragma unroll
    for (int mt = 0; mt < 2; mt++)
#pragma unroll
        for (int nt = 0; nt < 8; nt++)
#pragma unroll
            for (int q = 0; q < 4; q++) acc[mt][nt][q] = 0.f;

    auto load_B2 = [&](int t, int buf) {
        const __half* bsrc = g_WtF + t*32;
        uint32_t sbb = s_u + (uint32_t)buf*8192;     // reuse A-staging region
#pragma unroll
        for (int i = 0; i < 2; i++) {
            int id = tid + i*256;
            int o = id & 3, n = id >> 2;
            cpa16(sbb + (uint32_t)(o*2048 + n*16), bsrc + (size_t)n*256 + o*8);
        }
        CP_COMMIT();
    };

    load_B2(0, 0);
    int buf2 = 0;
    for (int t = 0; t < 8; t++) {
        CP_WAIT0();
        __syncthreads();
        if (t + 1 < 8) load_B2(t + 1, buf2 ^ 1);

        uint32_t abase = uv_u + (uint32_t)((t >> 2)*32768 + (t & 3)*8192);
        uint32_t sbb = s_u + (uint32_t)buf2*8192;
#pragma unroll
        for (int s = 0; s < 2; s++) {
            uint32_t a[2][4], b[4][4];
#pragma unroll
            for (int mt = 0; mt < 2; mt++)
                ldm4(a[mt], abase + (uint32_t)s*4096 + aoff[mt]);
#pragma unroll
            for (int ntp = 0; ntp < 4; ntp++)
                ldm4(b[ntp], sbb + (uint32_t)s*4096 + boff[ntp]);
#pragma unroll
            for (int mt = 0; mt < 2; mt++)
#pragma unroll
                for (int ntp = 0; ntp < 4; ntp++) {
                    mma_f16(acc[mt][ntp*2 + 0], a[mt], b[ntp][0], b[ntp][2]);
                    mma_f16(acc[mt][ntp*2 + 1], a[mt], b[ntp][1], b[ntp][3]);
                }
        }
        __syncthreads();
        buf2 ^= 1;
    }

    // epilogue: stage [64 c][128 pix] fp32 (in dead U/V region), write NCHW coalesced
    {
        const float* biasp = g_ba;
        float* SP = (float*)(smf + 32768);           // 33024 B fits in U+V region
        const int n_img = p0 / HWD, hw0 = p0 % HWD;
        float* obase = out + (size_t)n_img*CDIM*HWD + hw0;
#pragma unroll
        for (int ch = 0; ch < 2; ch++) {
            if ((wid >> 2) == ch) {
#pragma unroll
                for (int nt = 0; nt < 8; nt++) {
                    int cb = nt*8 + (lane & 3)*2;
                    float b0 = biasp[ch*64 + cb], b1 = biasp[ch*64 + cb + 1];
#pragma unroll
                    for (int mt = 0; mt < 2; mt++)
#pragma unroll
                        for (int half = 0; half < 2; half++) {
                            int row = wm + (lane >> 2) + mt*16 + half*8;
                            SP[cb*129 + row]     = fmaxf(acc[mt][nt][half*2 + 0] + b0, 0.f);
                            SP[(cb+1)*129 + row] = fmaxf(acc[mt][nt][half*2 + 1] + b1, 0.f);
                        }
                }
            }
            __syncthreads();
#pragma unroll
            for (int t2 = 0; t2 < 32; t2++) {
                int id = tid + t2*256;
                int c = id >> 7, pix = id & 127;
                obase[(size_t)(ch*64 + c)*HWD + pix] = SP[c*129 + pix];
            }
            __syncthreads();
        }
    }
}

// ---------------- axial attention: FA-style on mma.sync fp16 (unchanged from R12) ----------------
__global__ __launch_bounds__(256, 2) void attn_kernel() {
    extern __shared__ char smc[];
    uint32_t s_u = (uint32_t)__cvta_generic_to_shared(smc);
    uint32_t q_u = s_u, k_u = s_u + 16384, v_u = s_u + 32768, p_u = s_u + 49152;
    float* pmax = (float*)(smc + 57344);
    float* psum = (float*)(smc + 57856);

    const int tid = threadIdx.x;
    const int wid = tid >> 5, lane = tid & 31;
    const int q0 = blockIdx.x * 64;
    const int brow_idx = blockIdx.y;
    const int dir = blockIdx.z;

    size_t base; int stride;
    if (dir == 0) { base = (size_t)brow_idx * LROW * CDIM; stride = CDIM; }
    else {
        int n = brow_idx / WW, w = brow_idx % WW;
        base = (size_t)n*HH*WW*CDIM + (size_t)w*CDIM;
        stride = WW*CDIM;
    }
    const __half* thp = g_th + base;
    const __half* php = g_ph + base;
    const __half* gp  = g_g  + base;
    __half* outp = (dir == 0 ? g_ah : g_av) + base;

#pragma unroll
    for (int t = 0; t < 4; t++) {
        int id = tid + t*256;
        int i = id >> 4, g = id & 15;
        cpa16(q_u + (uint32_t)(i*256 + ((g ^ (i & 7)) << 4)),
              thp + (size_t)(q0 + i)*stride + g*8);
    }
    CP_COMMIT();

    const int l15 = lane & 15, lg = lane >> 4;
    const int frow = lane >> 2, fcol2 = (lane & 3)*2;
    const int wm = (wid & 3) * 16;
    const int wnsI = wid >> 2;
    const int wns = wnsI * 32, wnp = wnsI * 64;

    const int rowA = wm + l15;
    const uint32_t qbase = q_u + rowA*256;
    const uint32_t pbase = p_u + rowA*128;
    const int xA = rowA & 7;
    const int rowK0 = wns + l15, rowK1 = wns + 16 + l15;
    const uint32_t kb0 = k_u + rowK0*256, kb1 = k_u + rowK1*256;
    const int xK0 = rowK0 & 7, xK1 = rowK1 & 7;
    const int jrow = (lane & 7) + (lane & 8);
    const uint32_t vbase = v_u + jrow*256;
    const int jx = lane & 7;
    uint32_t voff[4];
#pragma unroll
    for (int ntp = 0; ntp < 4; ntp++)
        voff[ntp] = (uint32_t)((((wnp >> 3) + ntp*2 + lg) ^ jx) << 4);

    float o[8][4];
#pragma unroll
    for (int nt = 0; nt < 8; nt++)
#pragma unroll
        for (int q = 0; q < 4; q++) o[nt][q] = 0.f;
    float m0 = -1e30f, m1 = -1e30f, l0 = 0.f, l1 = 0.f;
    const float scale = 0.08838834764831845f;

    for (int kb = 0; kb < LROW; kb += 64) {
        __syncthreads();
#pragma unroll
        for (int t = 0; t < 4; t++) {
            int id = tid + t*256;
            int j = id >> 4, g = id & 15;
            cpa16(k_u + (uint32_t)(j*256 + ((g ^ (j & 7)) << 4)),
                  php + (size_t)(kb + j)*stride + g*8);
        }
        CP_COMMIT();
#pragma unroll
        for (int t = 0; t < 4; t++) {
            int id = tid + t*256;
            int j = id >> 4, g = id & 15;
            cpa16(v_u + (uint32_t)(j*256 + ((g ^ (j & 7)) << 4)),
                  gp + (size_t)(kb + j)*stride + g*8);
        }
        CP_COMMIT();
        CP_WAIT1();
        __syncthreads();

        float sacc[4][4];
#pragma unroll
        for (int nt = 0; nt < 4; nt++)
#pragma unroll
            for (int q = 0; q < 4; q++) sacc[nt][q] = 0.f;
#pragma unroll
        for (int s = 0; s < 8; s++) {
            uint32_t a[4], b0[4], b1[4];
            ldm4(a,  qbase + (uint32_t)(((2*s + lg) ^ xA)  << 4));
            ldm4(b0, kb0   + (uint32_t)(((2*s + lg) ^ xK0) << 4));
            ldm4(b1, kb1   + (uint32_t)(((2*s + lg) ^ xK1) << 4));
            mma_f16(sacc[0], a, b0[0], b0[2]);
            mma_f16(sacc[1], a, b0[1], b0[3]);
            mma_f16(sacc[2], a, b1[0], b1[2]);
            mma_f16(sacc[3], a, b1[1], b1[3]);
        }

        float r0 = -1e30f, r1 = -1e30f;
#pragma unroll
        for (int nt = 0; nt < 4; nt++) {
            sacc[nt][0] *= scale; sacc[nt][1] *= scale;
            sacc[nt][2] *= scale; sacc[nt][3] *= scale;
            r0 = fmaxf(r0, fmaxf(sacc[nt][0], sacc[nt][1]));
            r1 = fmaxf(r1, fmaxf(sacc[nt][2], sacc[nt][3]));
        }
        r0 = fmaxf(r0, __shfl_xor_sync(0xffffffffu, r0, 1));
        r0 = fmaxf(r0, __shfl_xor_sync(0xffffffffu, r0, 2));
        r1 = fmaxf(r1, __shfl_xor_sync(0xffffffffu, r1, 1));
        r1 = fmaxf(r1, __shfl_xor_sync(0xffffffffu, r1, 2));
        if ((lane & 3) == 0) {
            pmax[wnsI*64 + wm + frow]     = r0;
            pmax[wnsI*64 + wm + 8 + frow] = r1;
        }
        __syncthreads();

        const int ro0 = wm + frow, ro1 = ro0 + 8;
        float mn0 = fmaxf(m0, fmaxf(pmax[ro0], pmax[64 + ro0]));
        float mn1 = fmaxf(m1, fmaxf(pmax[ro1], pmax[64 + ro1]));
        float al0 = __expf(m0 - mn0), al1 = __expf(m1 - mn1);
        float s0a = 0.f, s1a = 0.f;
#pragma unroll
        for (int nt = 0; nt < 4; nt++) {
            __half2 h01 = __floats2half2_rn(__expf(sacc[nt][0] - mn0), __expf(sacc[nt][1] - mn0));
            __half2 h23 = __floats2half2_rn(__expf(sacc[nt][2] - mn1), __expf(sacc[nt][3] - mn1));
            int jg = wnsI*4 + nt;
            *(__half2*)(smc + 49152 + ro0*128 + ((jg ^ (ro0 & 7)) << 4) + fcol2*2) = h01;
            *(__half2*)(smc + 49152 + ro1*128 + ((jg ^ (ro1 & 7)) << 4) + fcol2*2) = h23;
            float2 e01 = __half22float2(h01), e23 = __half22float2(h23);
            s0a += e01.x + e01.y; s1a += e23.x + e23.y;
        }
        s0a += __shfl_xor_sync(0xffffffffu, s0a, 1);
        s0a += __shfl_xor_sync(0xffffffffu, s0a, 2);
        s1a += __shfl_xor_sync(0xffffffffu, s1a, 1);
        s1a += __shfl_xor_sync(0xffffffffu, s1a, 2);
        if ((lane & 3) == 0) {
            psum[wnsI*64 + ro0] = s0a;
            psum[wnsI*64 + ro1] = s1a;
        }
        CP_WAIT0();
        __syncthreads();

        l0 = l0*al0 + (psum[ro0] + psum[64 + ro0]);
        l1 = l1*al1 + (psum[ro1] + psum[64 + ro1]);
        m0 = mn0; m1 = mn1;
#pragma unroll
        for (int nt = 0; nt < 8; nt++) {
            o[nt][0] *= al0; o[nt][1] *= al0;
            o[nt][2] *= al1; o[nt][3] *= al1;
        }

#pragma unroll
        for (int s = 0; s < 4; s++) {
            uint32_t pa[4];
            ldm4(pa, pbase + (uint32_t)(((2*s + lg) ^ xA) << 4));
#pragma unroll
            for (int ntp = 0; ntp < 4; ntp++) {
                uint32_t vb[4];
                ldm4t(vb, vbase + (uint32_t)s*4096 + voff[ntp]);
                mma_f16(o[ntp*2 + 0], pa, vb[0], vb[1]);
                mma_f16(o[ntp*2 + 1], pa, vb[2], vb[3]);
            }
        }
    }

    {
        float inv0 = 1.f / l0, inv1 = 1.f / l1;
        int r0w = q0 + wm + frow;
#pragma unroll
        for (int nt = 0; nt < 8; nt++) {
            int cb = wnp + nt*8 + fcol2;
            *(__half2*)(outp + (size_t)r0w*stride + cb) =
                __floats2half2_rn(o[nt][0]*inv0, o[nt][1]*inv0);
            *(__half2*)(outp + (size_t)(r0w + 8)*stride + cb) =
                __floats2half2_rn(o[nt][2]*inv1, o[nt][3]*inv1);
        }
    }
}

// ---------------- launch ----------------
extern "C" void kernel_launch(void* const* d_in, const int* in_sizes, int n_in,
                              void* d_out, int out_size) {
    const float* f  = (const float*)d_in[0];
    const float* W7 = (const float*)d_in[1];
    const float* m7 = (const float*)d_in[2];
    const float* v7 = (const float*)d_in[3];
    const float* b7 = (const float*)d_in[4];
    const float* Wa = (const float*)d_in[5];
    const float* ma = (const float*)d_in[6];
    const float* va = (const float*)d_in[7];
    const float* ba = (const float*)d_in[8];
    float* out = (float*)d_out;

    prep_kernel<<<64, 256>>>(W7, m7, v7, b7, Wa, ma, va, ba);

    transpose_in<<<dim3(HWD/32, CDIM/32, NB), dim3(32, 8)>>>(f);

    gemm0_kernel<<<dim3(5, PTOT/128), 256>>>();

    int smem_attn = 58368;
    cudaFuncSetAttribute(attn_kernel, cudaFuncAttributeMaxDynamicSharedMemorySize, smem_attn);
    attn_kernel<<<dim3(LROW/64, NROWS, 2), 256, smem_attn>>>();

    int smem_fused = 98304;
    cudaFuncSetAttribute(fusedc_kernel, cudaFuncAttributeMaxDynamicSharedMemorySize, smem_fused);
    fusedc_kernel<<<PTOT/128, 256, smem_fused>>>(out);
}

// round 14
// speedup vs baseline: 1.8572x; 1.1133x over previous
#include <cuda_runtime.h>
#include <cuda_fp16.h>
#include <math.h>
#include <cstdint>

#define NB 8
#define CDIM 128
#define HH 192
#define WW 192
#define HWD (HH*WW)          // 36864
#define PTOT (NB*HWD)        // 294912
#define LROW 192
#define NROWS (NB*HH)        // 1536
#define BN_EPS 1e-5f

// ---------------- cp.async / ldmatrix / mma helpers (family-portable) ----------------
__device__ __forceinline__ void cpa16(uint32_t s, const void* g) {
    asm volatile("cp.async.ca.shared.global [%0], [%1], 16;" :: "r"(s), "l"(g));
}
#define CP_COMMIT() asm volatile("cp.async.commit_group;" ::: "memory")
#define CP_WAIT0()  asm volatile("cp.async.wait_group 0;" ::: "memory")
#define CP_WAIT1()  asm volatile("cp.async.wait_group 1;" ::: "memory")

__device__ __forceinline__ void ldm4(uint32_t* r, uint32_t addr) {
    asm volatile("ldmatrix.sync.aligned.m8n8.x4.shared.b16 {%0,%1,%2,%3}, [%4];"
                 : "=r"(r[0]), "=r"(r[1]), "=r"(r[2]), "=r"(r[3]) : "r"(addr));
}
__device__ __forceinline__ void ldm4t(uint32_t* r, uint32_t addr) {
    asm volatile("ldmatrix.sync.aligned.m8n8.x4.trans.shared.b16 {%0,%1,%2,%3}, [%4];"
                 : "=r"(r[0]), "=r"(r[1]), "=r"(r[2]), "=r"(r[3]) : "r"(addr));
}
__device__ __forceinline__ void mma_f16(float* d, const uint32_t* a, uint32_t b0, uint32_t b1) {
    asm volatile(
        "mma.sync.aligned.m16n8k16.row.col.f32.f16.f16.f32 "
        "{%0,%1,%2,%3}, {%4,%5,%6,%7}, {%8,%9}, {%0,%1,%2,%3};"
        : "+f"(d[0]), "+f"(d[1]), "+f"(d[2]), "+f"(d[3])
        : "r"(a[0]), "r"(a[1]), "r"(a[2]), "r"(a[3]), "r"(b0), "r"(b1));
}

// ---------------- device scratch ----------------
__device__ __half g_th [PTOT*CDIM];   // theta (fp16)
__device__ __half g_ph [PTOT*CDIM];   // phi
__device__ __half g_g  [PTOT*CDIM];   // g
__device__ __half g_ah [PTOT*CDIM];   // attn-h out
__device__ __half g_av [PTOT*CDIM];   // attn-v out
__device__ __half g_sch[PTOT*CDIM];
__device__ __half g_scv[PTOT*CDIM];

__device__ __half g_WtA[5*CDIM*CDIM]; // [mat][d][k]
__device__ float  g_biasA[5*CDIM];
__device__ __half g_Wt3[CDIM*CDIM];
__device__ float  g_b3[CDIM];
__device__ __half g_Wt5[CDIM*CDIM];
__device__ float  g_b5[CDIM];
__device__ __half g_WtF[CDIM*2*CDIM]; // [d][256]
__device__ float  g_ba[CDIM];

// ---------------- BN folding prep (fp16 weights) ----------------
__global__ void prep_kernel(const float* __restrict__ W7, const float* __restrict__ m7,
                            const float* __restrict__ v7, const float* __restrict__ b7,
                            const float* __restrict__ Wa, const float* __restrict__ ma,
                            const float* __restrict__ va, const float* __restrict__ ba) {
    int t = blockIdx.x * blockDim.x + threadIdx.x;
    int stride = gridDim.x * blockDim.x;
    const int mats[5] = {0, 1, 2, 4, 6};
    for (int idx = t; idx < 5*128*128; idx += stride) {
        int m = idx >> 14, r = idx & 16383, d = r >> 7, k = r & 127;
        int mm = mats[m];
        float rs = rsqrtf(v7[mm*128 + d] + BN_EPS);
        g_WtA[idx] = __float2half_rn(W7[(mm*128 + k)*128 + d] * rs);
        if (k == 0) g_biasA[m*128 + d] = b7[mm*128 + d] - m7[mm*128 + d]*rs;
    }
    for (int idx = t; idx < 128*128; idx += stride) {
        int d = idx >> 7, k = idx & 127;
        float rs3 = rsqrtf(v7[3*128 + d] + BN_EPS);
        float rs5 = rsqrtf(v7[5*128 + d] + BN_EPS);
        g_Wt3[idx] = __float2half_rn(W7[(3*128 + k)*128 + d] * rs3);
        g_Wt5[idx] = __float2half_rn(W7[(5*128 + k)*128 + d] * rs5);
        if (k == 0) {
            g_b3[d] = b7[3*128 + d] - m7[3*128 + d]*rs3;
            g_b5[d] = b7[5*128 + d] - m7[5*128 + d]*rs5;
        }
    }
    for (int idx = t; idx < 128*256; idx += stride) {
        int d = idx >> 8, kk = idx & 255;
        float rs = rsqrtf(va[d] + BN_EPS);
        g_WtF[idx] = __float2half_rn(Wa[kk*128 + d] * rs);
        if (kk == 0) g_ba[d] = ba[d] - ma[d]*rs;
    }
}

// ---------------- stage A: fused NCHW load/transpose + 5-mat GEMM ----------------
// dyn smem: fp32 staging [2][32*132] @0 (33792) | A fp16 planes 32KB @33792 | B [2][8KB] @66560
__global__ __launch_bounds__(256, 2) void gemm0_kernel(const float* __restrict__ f) {
    extern __shared__ __align__(16) char smg[];
    const int tid = threadIdx.x;
    const int wid = tid >> 5, lane = tid & 31;
    const int p0 = blockIdx.x * 128;
    const int wm = (wid & 3) * 32;
    const int wn = (wid >> 2) * 64;

    uint32_t s_u = (uint32_t)__cvta_generic_to_shared(smg);
    uint32_t st_u = s_u;
    uint32_t a_u = s_u + 33792;
    uint32_t b_u = s_u + 66560;

    const int n_img = p0 / HWD, hw0 = p0 % HWD;
    const float* fsrc = f + (size_t)n_img*CDIM*HWD + hw0;

    const int l15 = lane & 15, lg = lane >> 4;
    uint32_t aoff[2], boff[4];
#pragma unroll
    for (int mt = 0; mt < 2; mt++)
        aoff[mt] = (uint32_t)(lg*2048 + (wm + mt*16 + l15)*16);
#pragma unroll
    for (int ntp = 0; ntp < 4; ntp++)
        boff[ntp] = (uint32_t)(lg*2048 + (wn + ntp*16 + l15)*16);

    // ---- Phase A: load fp32 NCHW slices, convert to fp16 plane layout ----
    auto load_stg = [&](int t, int buf) {
        const float* src = fsrc + (size_t)t*32*HWD;
#pragma unroll
        for (int i = 0; i < 4; i++) {
            int id = tid + i*256;                // 1024 16B chunks
            int c = id >> 5, q = id & 31;
            cpa16(st_u + (uint32_t)buf*16896 + (uint32_t)(c*132 + q*4)*4,
                  src + (size_t)c*HWD + q*4);
        }
        CP_COMMIT();
    };
    load_stg(0, 0);
    const int pix = tid >> 1, hh = tid & 1;
    for (int t = 0; t < 4; t++) {
        CP_WAIT0();
        __syncthreads();
        if (t + 1 < 4) load_stg(t + 1, (t + 1) & 1);
        const float* STG = (const float*)(smg + (t & 1)*16896);
        float v[16];
#pragma unroll
        for (int i = 0; i < 16; i++) v[i] = STG[(hh*16 + i)*132 + pix];
        char* AP = smg + 33792 + t*8192;
#pragma unroll
        for (int i = 0; i < 16; i += 4) {
            int k = hh*16 + i;
            __half2 lo = __floats2half2_rn(v[i],   v[i+1]);
            __half2 hi = __floats2half2_rn(v[i+2], v[i+3]);
            uint2 pk;
            pk.x = *(uint32_t*)&lo; pk.y = *(uint32_t*)&hi;
            *(uint2*)(AP + (k >> 3)*2048 + pix*16 + (k & 7)*2) = pk;
        }
    }
    __syncthreads();   // A fully resident

    // ---- Phase B: 5 mats against resident A, B double-buffered ----
    auto load_B = [&](int m, int t, int buf) {
        const __half* bsrc = g_WtA + m*16384 + t*32;
#pragma unroll
        for (int i = 0; i < 2; i++) {
            int id = tid + i*256;
            int o = id & 3, n = id >> 2;
            cpa16(b_u + (uint32_t)buf*8192 + (uint32_t)(o*2048 + n*16),
                  bsrc + (size_t)n*128 + o*8);
        }
        CP_COMMIT();
    };

    load_B(0, 0, 0);
    int buf = 0;
    float acc[2][8][4];
#pragma unroll 1
    for (int m = 0; m < 5; m++) {
#pragma unroll
        for (int mt = 0; mt < 2; mt++)
#pragma unroll
            for (int nt = 0; nt < 8; nt++)
#pragma unroll
                for (int q = 0; q < 4; q++) acc[mt][nt][q] = 0.f;

        for (int t = 0; t < 4; t++) {
            int step = m*4 + t;
            CP_WAIT0();
            __syncthreads();
            if (step + 1 < 20) load_B((step + 1) >> 2, (step + 1) & 3, buf ^ 1);

            uint32_t abase = a_u + (uint32_t)t*8192;
            uint32_t sbb = b_u + (uint32_t)buf*8192;
#pragma unroll
            for (int s = 0; s < 2; s++) {
                uint32_t a[2][4], b[4][4];
#pragma unroll
                for (int mt = 0; mt < 2; mt++)
                    ldm4(a[mt], abase + (uint32_t)s*4096 + aoff[mt]);
#pragma unroll
                for (int ntp = 0; ntp < 4; ntp++)
                    ldm4(b[ntp], sbb + (uint32_t)s*4096 + boff[ntp]);
#pragma unroll
                for (int mt = 0; mt < 2; mt++)
#pragma unroll
                    for (int ntp = 0; ntp < 4; ntp++) {
                        mma_f16(acc[mt][ntp*2 + 0], a[mt], b[ntp][0], b[ntp][2]);
                        mma_f16(acc[mt][ntp*2 + 1], a[mt], b[ntp][1], b[ntp][3]);
                    }
            }
            __syncthreads();
            buf ^= 1;
        }

        // epilogue for mat m
        __half* houtp = (m==0) ? g_th : (m==1) ? g_ph : (m==2) ? g_g : (m==3) ? g_sch : g_scv;
        const float* biasp = g_biasA + m*128;
        const bool relu = (m < 3);
        const int rbase = p0 + wm + (lane >> 2);
#pragma unroll
        for (int nt = 0; nt < 8; nt++) {
            int cb = wn + nt*8 + (lane & 3)*2;
            float b0 = biasp[cb], b1 = biasp[cb + 1];
#pragma unroll
            for (int mt = 0; mt < 2; mt++) {
#pragma unroll
                for (int half = 0; half < 2; half++) {
                    int row = rbase + mt*16 + half*8;
                    size_t ro = (size_t)row*128 + cb;
                    float v0 = acc[mt][nt][half*2 + 0] + b0;
                    float v1 = acc[mt][nt][half*2 + 1] + b1;
                    if (relu) { v0 = fmaxf(v0, 0.f); v1 = fmaxf(v1, 0.f); }
                    *(__half2*)(houtp + ro) = __floats2half2_rn(v0, v1);
                }
            }
        }
    }
}

// ---------------- fused C-stage (unchanged from R13) ----------------
__global__ __launch_bounds__(256, 2) void fusedc_kernel(float* __restrict__ out) {
    extern __shared__ __align__(16) char smf[];
    const int tid = threadIdx.x;
    const int wid = tid >> 5, lane = tid & 31;
    const int p0 = blockIdx.x * 128;
    const int wm = (wid & 3) * 32;
    const int wn = (wid >> 2) * 64;

    uint32_t s_u = (uint32_t)__cvta_generic_to_shared(smf);
    uint32_t sa_u = s_u, sb_u = s_u + 16384;
    uint32_t uv_u = s_u + 32768;

    const int l15 = lane & 15, lg = lane >> 4;
    uint32_t aoff[2], boff[4];
#pragma unroll
    for (int mt = 0; mt < 2; mt++)
        aoff[mt] = (uint32_t)(lg*2048 + (wm + mt*16 + l15)*16);
#pragma unroll
    for (int ntp = 0; ntp < 4; ntp++)
        boff[ntp] = (uint32_t)(lg*2048 + (wn + ntp*16 + l15)*16);

    float acc[2][8][4];

#pragma unroll 1
    for (int y = 0; y < 2; y++) {
        const __half* Abase0 = y ? g_av : g_ah;
        const __half* Bp = y ? g_Wt5 : g_Wt3;
        const __half* scp = (y ? g_scv : g_sch) + (size_t)p0*128;
        const float* biasp = y ? g_b5 : g_b3;
        char* UV = smf + 32768 + y*32768;

#pragma unroll
        for (int mt = 0; mt < 2; mt++)
#pragma unroll
            for (int nt = 0; nt < 8; nt++)
#pragma unroll
                for (int q = 0; q < 4; q++) acc[mt][nt][q] = 0.f;

        auto load_tile = [&](int t, int buf) {
            int k0 = t * 32;
            const __half* asrc = Abase0 + (size_t)p0*128 + k0;
            uint32_t sab = sa_u + (uint32_t)buf*8192;
            uint32_t sbb = sb_u + (uint32_t)buf*8192;
#pragma unroll
            for (int i = 0; i < 2; i++) {
                int id = tid + i*256;
                int o = id & 3, r = id >> 2;
                cpa16(sab + (uint32_t)(o*2048 + r*16), asrc + (size_t)r*128 + o*8);
            }
            const __half* bsrc = Bp + k0;
#pragma unroll
            for (int i = 0; i < 2; i++) {
                int id = tid + i*256;
                int o = id & 3, n = id >> 2;
                cpa16(sbb + (uint32_t)(o*2048 + n*16), bsrc + (size_t)n*128 + o*8);
            }
            CP_COMMIT();
        };

        load_tile(0, 0);
        int buf = 0;
        for (int t = 0; t < 4; t++) {
            CP_WAIT0();
            __syncthreads();
            if (t + 1 < 4) load_tile(t + 1, buf ^ 1);

            uint32_t sab = sa_u + (uint32_t)buf*8192;
            uint32_t sbb = sb_u + (uint32_t)buf*8192;
#pragma unroll
            for (int s = 0; s < 2; s++) {
                uint32_t a[2][4], b[4][4];
#pragma unroll
                for (int mt = 0; mt < 2; mt++)
                    ldm4(a[mt], sab + (uint32_t)s*4096 + aoff[mt]);
#pragma unroll
                for (int ntp = 0; ntp < 4; ntp++)
                    ldm4(b[ntp], sbb + (uint32_t)s*4096 + boff[ntp]);
#pragma unroll
                for (int mt = 0; mt < 2; mt++)
#pragma unroll
                    for (int ntp = 0; ntp < 4; ntp++) {
                        mma_f16(acc[mt][ntp*2 + 0], a[mt], b[ntp][0], b[ntp][2]);
                        mma_f16(acc[mt][ntp*2 + 1], a[mt], b[ntp][1], b[ntp][3]);
                    }
            }
            __syncthreads();
            buf ^= 1;
        }

#pragma unroll
        for (int nt = 0; nt < 8; nt++) {
            int cb = wn + nt*8 + (lane & 3)*2;
            float b0 = biasp[cb], b1 = biasp[cb + 1];
            uint32_t pl = (uint32_t)((cb >> 5)*8192 + ((cb >> 3) & 3)*2048 + (cb & 7)*2);
#pragma unroll
            for (int mt = 0; mt < 2; mt++) {
#pragma unroll
                for (int half = 0; half < 2; half++) {
                    int row = wm + (lane >> 2) + mt*16 + half*8;
                    float2 sc = __half22float2(*(const __half2*)(scp + (size_t)row*128 + cb));
                    float v0 = fmaxf(acc[mt][nt][half*2 + 0] + b0 + sc.x, 0.f);
                    float v1 = fmaxf(acc[mt][nt][half*2 + 1] + b1 + sc.y, 0.f);
                    *(__half2*)(UV + pl + row*16) = __floats2half2_rn(v0, v1);
                }
            }
        }
        __syncthreads();
    }

#pragma unroll
    for (int mt = 0; mt < 2; mt++)
#pragma unroll
        for (int nt = 0; nt < 8; nt++)
#pragma unroll
            for (int q = 0; q < 4; q++) acc[mt][nt][q] = 0.f;

    auto load_B2 = [&](int t, int buf) {
        const __half* bsrc = g_WtF + t*32;
        uint32_t sbb = s_u + (uint32_t)buf*8192;
#pragma unroll
        for (int i = 0; i < 2; i++) {
            int id = tid + i*256;
            int o = id & 3, n = id >> 2;
            cpa16(sbb + (uint32_t)(o*2048 + n*16), bsrc + (size_t)n*256 + o*8);
        }
        CP_COMMIT();
    };

    load_B2(0, 0);
    int buf2 = 0;
    for (int t = 0; t < 8; t++) {
        CP_WAIT0();
        __syncthreads();
        if (t + 1 < 8) load_B2(t + 1, buf2 ^ 1);

        uint32_t abase = uv_u + (uint32_t)((t >> 2)*32768 + (t & 3)*8192);
        uint32_t sbb = s_u + (uint32_t)buf2*8192;
#pragma unroll
        for (int s = 0; s < 2; s++) {
            uint32_t a[2][4], b[4][4];
#pragma unroll
            for (int mt = 0; mt < 2; mt++)
                ldm4(a[mt], abase + (uint32_t)s*4096 + aoff[mt]);
#pragma unroll
            for (int ntp = 0; ntp < 4; ntp++)
                ldm4(b[ntp], sbb + (uint32_t)s*4096 + boff[ntp]);
#pragma unroll
            for (int mt = 0; mt < 2; mt++)
#pragma unroll
                for (int ntp = 0; ntp < 4; ntp++) {
                    mma_f16(acc[mt][ntp*2 + 0], a[mt], b[ntp][0], b[ntp][2]);
                    mma_f16(acc[mt][ntp*2 + 1], a[mt], b[ntp][1], b[ntp][3]);
                }
        }
        __syncthreads();
        buf2 ^= 1;
    }

    {
        const float* biasp = g_ba;
        float* SP = (float*)(smf + 32768);
        const int n_img = p0 / HWD, hw0 = p0 % HWD;
        float* obase = out + (size_t)n_img*CDIM*HWD + hw0;
#pragma unroll
        for (int ch = 0; ch < 2; ch++) {
            if ((wid >> 2) == ch) {
#pragma unroll
                for (int nt = 0; nt < 8; nt++) {
                    int cb = nt*8 + (lane & 3)*2;
                    float b0 = biasp[ch*64 + cb], b1 = biasp[ch*64 + cb + 1];
#pragma unroll
                    for (int mt = 0; mt < 2; mt++)
#pragma unroll
                        for (int half = 0; half < 2; half++) {
                            int row = wm + (lane >> 2) + mt*16 + half*8;
                            SP[cb*129 + row]     = fmaxf(acc[mt][nt][half*2 + 0] + b0, 0.f);
                            SP[(cb+1)*129 + row] = fmaxf(acc[mt][nt][half*2 + 1] + b1, 0.f);
                        }
                }
            }
            __syncthreads();
#pragma unroll
            for (int t2 = 0; t2 < 32; t2++) {
                int id = tid + t2*256;
                int c = id >> 7, pix = id & 127;
                obase[(size_t)(ch*64 + c)*HWD + pix] = SP[c*129 + pix];
            }
            __syncthreads();
        }
    }
}

// ---------------- axial attention: fp16 FA with K/V double-buffered prefetch ----------------
// smem: Q 16KB @0 | K[2] 32KB @16384 | V[2] 32KB @49152 | Ps 8KB @81920 |
//       pmax @90112 (512B) | psum @90624 (512B) ; total 91136
__global__ __launch_bounds__(256, 2) void attn_kernel() {
    extern __shared__ char smc[];
    uint32_t s_u = (uint32_t)__cvta_generic_to_shared(smc);
    uint32_t q_u = s_u, k_u = s_u + 16384, v_u = s_u + 49152, p_u = s_u + 81920;
    float* pmax = (float*)(smc + 90112);
    float* psum = (float*)(smc + 90624);

    const int tid = threadIdx.x;
    const int wid = tid >> 5, lane = tid & 31;
    const int q0 = blockIdx.x * 64;
    const int brow_idx = blockIdx.y;
    const int dir = blockIdx.z;

    size_t base; int stride;
    if (dir == 0) { base = (size_t)brow_idx * LROW * CDIM; stride = CDIM; }
    else {
        int n = brow_idx / WW, w = brow_idx % WW;
        base = (size_t)n*HH*WW*CDIM + (size_t)w*CDIM;
        stride = WW*CDIM;
    }
    const __half* thp = g_th + base;
    const __half* php = g_ph + base;
    const __half* gp  = g_g  + base;
    __half* outp = (dir == 0 ? g_ah : g_av) + base;

    auto fillK = [&](int kb, int buf) {
#pragma unroll
        for (int t = 0; t < 4; t++) {
            int id = tid + t*256;
            int j = id >> 4, g = id & 15;
            cpa16(k_u + (uint32_t)buf*16384 + (uint32_t)(j*256 + ((g ^ (j & 7)) << 4)),
                  php + (size_t)(kb + j)*stride + g*8);
        }
        CP_COMMIT();
    };
    auto fillV = [&](int kb, int buf) {
#pragma unroll
        for (int t = 0; t < 4; t++) {
            int id = tid + t*256;
            int j = id >> 4, g = id & 15;
            cpa16(v_u + (uint32_t)buf*16384 + (uint32_t)(j*256 + ((g ^ (j & 7)) << 4)),
                  gp + (size_t)(kb + j)*stride + g*8);
        }
        CP_COMMIT();
    };

    // Q fill (group 1), then K0 (g2), V0 (g3)
#pragma unroll
    for (int t = 0; t < 4; t++) {
        int id = tid + t*256;
        int i = id >> 4, g = id & 15;
        cpa16(q_u + (uint32_t)(i*256 + ((g ^ (i & 7)) << 4)),
              thp + (size_t)(q0 + i)*stride + g*8);
    }
    CP_COMMIT();
    fillK(0, 0);
    fillV(0, 0);

    const int l15 = lane & 15, lg = lane >> 4;
    const int frow = lane >> 2, fcol2 = (lane & 3)*2;
    const int wm = (wid & 3) * 16;
    const int wnsI = wid >> 2;
    const int wns = wnsI * 32, wnp = wnsI * 64;

    const int rowA = wm + l15;
    const uint32_t qbase = q_u + rowA*256;
    const uint32_t pbase = p_u + rowA*128;
    const int xA = rowA & 7;
    const int rowK0 = wns + l15, rowK1 = wns + 16 + l15;
    const int xK0 = rowK0 & 7, xK1 = rowK1 & 7;
    const int jrow = (lane & 7) + (lane & 8);
    const int jx = lane & 7;
    uint32_t voff[4];
#pragma unroll
    for (int ntp = 0; ntp < 4; ntp++)
        voff[ntp] = (uint32_t)((((wnp >> 3) + ntp*2 + lg) ^ jx) << 4);

    float o[8][4];
#pragma unroll
    for (int nt = 0; nt < 8; nt++)
#pragma unroll
        for (int q = 0; q < 4; q++) o[nt][q] = 0.f;
    float m0 = -1e30f, m1 = -1e30f, l0 = 0.f, l1 = 0.f;
    const float scale = 0.08838834764831845f;

    for (int c = 0; c < 3; c++) {
        const int kb = c*64;
        const uint32_t kcur = k_u + (uint32_t)(c & 1)*16384;
        const uint32_t vcur = v_u + (uint32_t)(c & 1)*16384;

        CP_WAIT1();        // K[c] (and Q on c=0) landed; V[c] may still be in flight
        __syncthreads();

        // S = Q K^T
        float sacc[4][4];
#pragma unroll
        for (int nt = 0; nt < 4; nt++)
#pragma unroll
            for (int q = 0; q < 4; q++) sacc[nt][q] = 0.f;
        const uint32_t kb0 = kcur + rowK0*256, kb1 = kcur + rowK1*256;
#pragma unroll
        for (int s = 0; s < 8; s++) {
            uint32_t a[4], b0[4], b1[4];
            ldm4(a,  qbase + (uint32_t)(((2*s + lg) ^ xA)  << 4));
            ldm4(b0, kb0   + (uint32_t)(((2*s + lg) ^ xK0) << 4));
            ldm4(b1, kb1   + (uint32_t)(((2*s + lg) ^ xK1) << 4));
            mma_f16(sacc[0], a, b0[0], b0[2]);
            mma_f16(sacc[1], a, b0[1], b0[3]);
            mma_f16(sacc[2], a, b1[0], b1[2]);
            mma_f16(sacc[3], a, b1[1], b1[3]);
        }
        if (c < 2) fillK(kb + 64, (c + 1) & 1);   // prefetch next K

        // softmax stage 1
        float r0 = -1e30f, r1 = -1e30f;
#pragma unroll
        for (int nt = 0; nt < 4; nt++) {
            sacc[nt][0] *= scale; sacc[nt][1] *= scale;
            sacc[nt][2] *= scale; sacc[nt][3] *= scale;
            r0 = fmaxf(r0, fmaxf(sacc[nt][0], sacc[nt][1]));
            r1 = fmaxf(r1, fmaxf(sacc[nt][2], sacc[nt][3]));
        }
        r0 = fmaxf(r0, __shfl_xor_sync(0xffffffffu, r0, 1));
        r0 = fmaxf(r0, __shfl_xor_sync(0xffffffffu, r0, 2));
        r1 = fmaxf(r1, __shfl_xor_sync(0xffffffffu, r1, 1));
        r1 = fmaxf(r1, __shfl_xor_sync(0xffffffffu, r1, 2));
        if ((lane & 3) == 0) {
            pmax[wnsI*64 + wm + frow]     = r0;
            pmax[wnsI*64 + wm + 8 + frow] = r1;
        }
        __syncthreads();

        // softmax stage 2
        const int ro0 = wm + frow, ro1 = ro0 + 8;
        float mn0 = fmaxf(m0, fmaxf(pmax[ro0], pmax[64 + ro0]));
        float mn1 = fmaxf(m1, fmaxf(pmax[ro1], pmax[64 + ro1]));
        float al0 = __expf(m0 - mn0), al1 = __expf(m1 - mn1);
        float s0a = 0.f, s1a = 0.f;
#pragma unroll
        for (int nt = 0; nt < 4; nt++) {
            __half2 h01 = __floats2half2_rn(__expf(sacc[nt][0] - mn0), __expf(sacc[nt][1] - mn0));
            __half2 h23 = __floats2half2_rn(__expf(sacc[nt][2] - mn1), __expf(sacc[nt][3] - mn1));
            int jg = wnsI*4 + nt;
            *(__half2*)(smc + 81920 + ro0*128 + ((jg ^ (ro0 & 7)) << 4) + fcol2*2) = h01;
            *(__half2*)(smc + 81920 + ro1*128 + ((jg ^ (ro1 & 7)) << 4) + fcol2*2) = h23;
            float2 e01 = __half22float2(h01), e23 = __half22float2(h23);
            s0a += e01.x + e01.y; s1a += e23.x + e23.y;
        }
        s0a += __shfl_xor_sync(0xffffffffu, s0a, 1);
        s0a += __shfl_xor_sync(0xffffffffu, s0a, 2);
        s1a += __shfl_xor_sync(0xffffffffu, s1a, 1);
        s1a += __shfl_xor_sync(0xffffffffu, s1a, 2);
        if ((lane & 3) == 0) {
            psum[wnsI*64 + ro0] = s0a;
            psum[wnsI*64 + ro1] = s1a;
        }
        if (c < 2) CP_WAIT1(); else CP_WAIT0();   // V[c] landed (next-K may stay pending)
        __syncthreads();

        l0 = l0*al0 + (psum[ro0] + psum[64 + ro0]);
        l1 = l1*al1 + (psum[ro1] + psum[64 + ro1]);
        m0 = mn0; m1 = mn1;
#pragma unroll
        for (int nt = 0; nt < 8; nt++) {
            o[nt][0] *= al0; o[nt][1] *= al0;
            o[nt][2] *= al1; o[nt][3] *= al1;
        }

        // O += P V
        const uint32_t vbase = vcur + jrow*256;
#pragma unroll
        for (int s = 0; s < 4; s++) {
            uint32_t pa[4];
            ldm4(pa, pbase + (uint32_t)(((2*s + lg) ^ xA) << 4));
#pragma unroll
            for (int ntp = 0; ntp < 4; ntp++) {
                uint32_t vb[4];
                ldm4t(vb, vbase + (uint32_t)s*4096 + voff[ntp]);
                mma_f16(o[ntp*2 + 0], pa, vb[0], vb[1]);
                mma_f16(o[ntp*2 + 1], pa, vb[2], vb[3]);
            }
        }
        if (c < 2) fillV(kb + 64, (c + 1) & 1);   // prefetch next V
    }

    {
        float inv0 = 1.f / l0, inv1 = 1.f / l1;
        int r0w = q0 + wm + frow;
#pragma unroll
        for (int nt = 0; nt < 8; nt++) {
            int cb = wnp + nt*8 + fcol2;
            *(__half2*)(outp + (size_t)r0w*stride + cb) =
                __floats2half2_rn(o[nt][0]*inv0, o[nt][1]*inv0);
            *(__half2*)(outp + (size_t)(r0w + 8)*stride + cb) =
                __floats2half2_rn(o[nt][2]*inv1, o[nt][3]*inv1);
        }
    }
}

// ---------------- launch ----------------
extern "C" void kernel_launch(void* const* d_in, const int* in_sizes, int n_in,
                              void* d_out, int out_size) {
    const float* f  = (const float*)d_in[0];
    const float* W7 = (const float*)d_in[1];
    const float* m7 = (const float*)d_in[2];
    const float* v7 = (const float*)d_in[3];
    const float* b7 = (const float*)d_in[4];
    const float* Wa = (const float*)d_in[5];
    const float* ma = (const float*)d_in[6];
    const float* va = (const float*)d_in[7];
    const float* ba = (const float*)d_in[8];
    float* out = (float*)d_out;

    prep_kernel<<<64, 256>>>(W7, m7, v7, b7, Wa, ma, va, ba);

    int smem_g0 = 82944;
    cudaFuncSetAttribute(gemm0_kernel, cudaFuncAttributeMaxDynamicSharedMemorySize, smem_g0);
    gemm0_kernel<<<PTOT/128, 256, smem_g0>>>(f);

    int smem_attn = 91136;
    cudaFuncSetAttribute(attn_kernel, cudaFuncAttributeMaxDynamicSharedMemorySize, smem_attn);
    attn_kernel<<<dim3(LROW/64, NROWS, 2), 256, smem_attn>>>();

    int smem_fused = 98304;
    cudaFuncSetAttribute(fusedc_kernel, cudaFuncAttributeMaxDynamicSharedMemorySize, smem_fused);
    fusedc_kernel<<<PTOT/128, 256, smem_fused>>>(out);
}

// round 15
// speedup vs baseline: 1.8706x; 1.0072x over previous
#include <cuda_runtime.h>
#include <cuda_fp16.h>
#include <math.h>
#include <cstdint>

#define NB 8
#define CDIM 128
#define HH 192
#define WW 192
#define HWD (HH*WW)          // 36864
#define PTOT (NB*HWD)        // 294912
#define LROW 192
#define NROWS (NB*HH)        // 1536
#define BN_EPS 1e-5f

// ---------------- cp.async / ldmatrix / mma helpers (family-portable) ----------------
__device__ __forceinline__ void cpa16(uint32_t s, const void* g) {
    asm volatile("cp.async.ca.shared.global [%0], [%1], 16;" :: "r"(s), "l"(g));
}
#define CP_COMMIT() asm volatile("cp.async.commit_group;" ::: "memory")
#define CP_WAIT0()  asm volatile("cp.async.wait_group 0;" ::: "memory")
#define CP_WAIT1()  asm volatile("cp.async.wait_group 1;" ::: "memory")

__device__ __forceinline__ void ldm4(uint32_t* r, uint32_t addr) {
    asm volatile("ldmatrix.sync.aligned.m8n8.x4.shared.b16 {%0,%1,%2,%3}, [%4];"
                 : "=r"(r[0]), "=r"(r[1]), "=r"(r[2]), "=r"(r[3]) : "r"(addr));
}
__device__ __forceinline__ void ldm4t(uint32_t* r, uint32_t addr) {
    asm volatile("ldmatrix.sync.aligned.m8n8.x4.trans.shared.b16 {%0,%1,%2,%3}, [%4];"
                 : "=r"(r[0]), "=r"(r[1]), "=r"(r[2]), "=r"(r[3]) : "r"(addr));
}
__device__ __forceinline__ void mma_f16(float* d, const uint32_t* a, uint32_t b0, uint32_t b1) {
    asm volatile(
        "mma.sync.aligned.m16n8k16.row.col.f32.f16.f16.f32 "
        "{%0,%1,%2,%3}, {%4,%5,%6,%7}, {%8,%9}, {%0,%1,%2,%3};"
        : "+f"(d[0]), "+f"(d[1]), "+f"(d[2]), "+f"(d[3])
        : "r"(a[0]), "r"(a[1]), "r"(a[2]), "r"(a[3]), "r"(b0), "r"(b1));
}

// ---------------- device scratch ----------------
__device__ __half g_th [PTOT*CDIM];   // theta (fp16)
__device__ __half g_ph [PTOT*CDIM];   // phi
__device__ __half g_g  [PTOT*CDIM];   // g
__device__ __half g_ah [PTOT*CDIM];   // attn-h out
__device__ __half g_av [PTOT*CDIM];   // attn-v out
__device__ __half g_sch[PTOT*CDIM];
__device__ __half g_scv[PTOT*CDIM];

__device__ __half g_WtA[5*CDIM*CDIM]; // [mat][d][k]
__device__ float  g_biasA[5*CDIM];
__device__ __half g_Wt3[CDIM*CDIM];
__device__ float  g_b3[CDIM];
__device__ __half g_Wt5[CDIM*CDIM];
__device__ float  g_b5[CDIM];
__device__ __half g_WtF[CDIM*2*CDIM]; // [d][256]
__device__ float  g_ba[CDIM];

// ---------------- BN folding prep (fp16 weights) ----------------
__global__ void prep_kernel(const float* __restrict__ W7, const float* __restrict__ m7,
                            const float* __restrict__ v7, const float* __restrict__ b7,
                            const float* __restrict__ Wa, const float* __restrict__ ma,
                            const float* __restrict__ va, const float* __restrict__ ba) {
    int t = blockIdx.x * blockDim.x + threadIdx.x;
    int stride = gridDim.x * blockDim.x;
    const int mats[5] = {0, 1, 2, 4, 6};
    for (int idx = t; idx < 5*128*128; idx += stride) {
        int m = idx >> 14, r = idx & 16383, d = r >> 7, k = r & 127;
        int mm = mats[m];
        float rs = rsqrtf(v7[mm*128 + d] + BN_EPS);
        g_WtA[idx] = __float2half_rn(W7[(mm*128 + k)*128 + d] * rs);
        if (k == 0) g_biasA[m*128 + d] = b7[mm*128 + d] - m7[mm*128 + d]*rs;
    }
    for (int idx = t; idx < 128*128; idx += stride) {
        int d = idx >> 7, k = idx & 127;
        float rs3 = rsqrtf(v7[3*128 + d] + BN_EPS);
        float rs5 = rsqrtf(v7[5*128 + d] + BN_EPS);
        g_Wt3[idx] = __float2half_rn(W7[(3*128 + k)*128 + d] * rs3);
        g_Wt5[idx] = __float2half_rn(W7[(5*128 + k)*128 + d] * rs5);
        if (k == 0) {
            g_b3[d] = b7[3*128 + d] - m7[3*128 + d]*rs3;
            g_b5[d] = b7[5*128 + d] - m7[5*128 + d]*rs5;
        }
    }
    for (int idx = t; idx < 128*256; idx += stride) {
        int d = idx >> 8, kk = idx & 255;
        float rs = rsqrtf(va[d] + BN_EPS);
        g_WtF[idx] = __float2half_rn(Wa[kk*128 + d] * rs);
        if (kk == 0) g_ba[d] = ba[d] - ma[d]*rs;
    }
}

// ---------------- stage A: fused NCHW transpose + 5-mat GEMM, 64x64 warp tiles ----------------
// 128 threads, 4 warps (2 M x 2 N). dyn smem: fp32 staging [2][32*132] @0 (33792) |
// A fp16 planes 32KB @33792 | B [2][8KB] @66560 ; total 82944
__global__ __launch_bounds__(128, 2) void gemm0_kernel(const float* __restrict__ f) {
    extern __shared__ __align__(16) char smg[];
    const int tid = threadIdx.x;
    const int wid = tid >> 5, lane = tid & 31;
    const int p0 = blockIdx.x * 128;
    const int wm = (wid & 1) * 64;
    const int wn = (wid >> 1) * 64;

    uint32_t s_u = (uint32_t)__cvta_generic_to_shared(smg);
    uint32_t st_u = s_u;
    uint32_t a_u = s_u + 33792;
    uint32_t b_u = s_u + 66560;

    const int n_img = p0 / HWD, hw0 = p0 % HWD;
    const float* fsrc = f + (size_t)n_img*CDIM*HWD + hw0;

    const int l15 = lane & 15, lg = lane >> 4;
    uint32_t aoff[4], boff[4];
#pragma unroll
    for (int mt = 0; mt < 4; mt++)
        aoff[mt] = (uint32_t)(lg*2048 + (wm + mt*16 + l15)*16);
#pragma unroll
    for (int ntp = 0; ntp < 4; ntp++)
        boff[ntp] = (uint32_t)(lg*2048 + (wn + ntp*16 + l15)*16);

    // ---- Phase A: load fp32 NCHW slices, convert to fp16 plane layout ----
    auto load_stg = [&](int t, int buf) {
        const float* src = fsrc + (size_t)t*32*HWD;
#pragma unroll
        for (int i = 0; i < 8; i++) {
            int id = tid + i*128;                // 1024 16B chunks
            int c = id >> 5, q = id & 31;
            cpa16(st_u + (uint32_t)buf*16896 + (uint32_t)(c*132 + q*4)*4,
                  src + (size_t)c*HWD + q*4);
        }
        CP_COMMIT();
    };
    load_stg(0, 0);
    for (int t = 0; t < 4; t++) {
        CP_WAIT0();
        __syncthreads();
        if (t + 1 < 4) load_stg(t + 1, (t + 1) & 1);
        const float* STG = (const float*)(smg + (t & 1)*16896);
        float v[32];
#pragma unroll
        for (int i = 0; i < 32; i++) v[i] = STG[i*132 + tid];
        char* AP = smg + 33792 + t*8192;
#pragma unroll
        for (int i = 0; i < 32; i += 4) {
            __half2 lo = __floats2half2_rn(v[i],   v[i+1]);
            __half2 hi = __floats2half2_rn(v[i+2], v[i+3]);
            uint2 pk;
            pk.x = *(uint32_t*)&lo; pk.y = *(uint32_t*)&hi;
            *(uint2*)(AP + (i >> 3)*2048 + tid*16 + (i & 7)*2) = pk;
        }
    }
    __syncthreads();   // A fully resident

    // ---- Phase B: 5 mats against resident A, B double-buffered ----
    auto load_B = [&](int m, int t, int buf) {
        const __half* bsrc = g_WtA + m*16384 + t*32;
#pragma unroll
        for (int i = 0; i < 4; i++) {
            int id = tid + i*128;
            int o = id & 3, n = id >> 2;
            cpa16(b_u + (uint32_t)buf*8192 + (uint32_t)(o*2048 + n*16),
                  bsrc + (size_t)n*128 + o*8);
        }
        CP_COMMIT();
    };

    load_B(0, 0, 0);
    int buf = 0;
    float acc[4][8][4];
#pragma unroll 1
    for (int m = 0; m < 5; m++) {
#pragma unroll
        for (int mt = 0; mt < 4; mt++)
#pragma unroll
            for (int nt = 0; nt < 8; nt++)
#pragma unroll
                for (int q = 0; q < 4; q++) acc[mt][nt][q] = 0.f;

        for (int t = 0; t < 4; t++) {
            int step = m*4 + t;
            CP_WAIT0();
            __syncthreads();
            if (step + 1 < 20) load_B((step + 1) >> 2, (step + 1) & 3, buf ^ 1);

            uint32_t abase = a_u + (uint32_t)t*8192;
            uint32_t sbb = b_u + (uint32_t)buf*8192;
#pragma unroll
            for (int s = 0; s < 2; s++) {
                uint32_t a[4][4], b[4][4];
#pragma unroll
                for (int mt = 0; mt < 4; mt++)
                    ldm4(a[mt], abase + (uint32_t)s*4096 + aoff[mt]);
#pragma unroll
                for (int ntp = 0; ntp < 4; ntp++)
                    ldm4(b[ntp], sbb + (uint32_t)s*4096 + boff[ntp]);
#pragma unroll
                for (int mt = 0; mt < 4; mt++)
#pragma unroll
                    for (int ntp = 0; ntp < 4; ntp++) {
                        mma_f16(acc[mt][ntp*2 + 0], a[mt], b[ntp][0], b[ntp][2]);
                        mma_f16(acc[mt][ntp*2 + 1], a[mt], b[ntp][1], b[ntp][3]);
                    }
            }
            __syncthreads();
            buf ^= 1;
        }

        // epilogue for mat m
        __half* houtp = (m==0) ? g_th : (m==1) ? g_ph : (m==2) ? g_g : (m==3) ? g_sch : g_scv;
        const float* biasp = g_biasA + m*128;
        const bool relu = (m < 3);
        const int rbase = p0 + wm + (lane >> 2);
#pragma unroll
        for (int nt = 0; nt < 8; nt++) {
            int cb = wn + nt*8 + (lane & 3)*2;
            float b0 = biasp[cb], b1 = biasp[cb + 1];
#pragma unroll
            for (int mt = 0; mt < 4; mt++) {
#pragma unroll
                for (int half = 0; half < 2; half++) {
                    int row = rbase + mt*16 + half*8;
                    size_t ro = (size_t)row*128 + cb;
                    float v0 = acc[mt][nt][half*2 + 0] + b0;
                    float v1 = acc[mt][nt][half*2 + 1] + b1;
                    if (relu) { v0 = fmaxf(v0, 0.f); v1 = fmaxf(v1, 0.f); }
                    *(__half2*)(houtp + ro) = __floats2half2_rn(v0, v1);
                }
            }
        }
    }
}

// ---------------- fused C-stage (unchanged from R14) ----------------
__global__ __launch_bounds__(256, 2) void fusedc_kernel(float* __restrict__ out) {
    extern __shared__ __align__(16) char smf[];
    const int tid = threadIdx.x;
    const int wid = tid >> 5, lane = tid & 31;
    const int p0 = blockIdx.x * 128;
    const int wm = (wid & 3) * 32;
    const int wn = (wid >> 2) * 64;

    uint32_t s_u = (uint32_t)__cvta_generic_to_shared(smf);
    uint32_t sa_u = s_u, sb_u = s_u + 16384;
    uint32_t uv_u = s_u + 32768;

    const int l15 = lane & 15, lg = lane >> 4;
    uint32_t aoff[2], boff[4];
#pragma unroll
    for (int mt = 0; mt < 2; mt++)
        aoff[mt] = (uint32_t)(lg*2048 + (wm + mt*16 + l15)*16);
#pragma unroll
    for (int ntp = 0; ntp < 4; ntp++)
        boff[ntp] = (uint32_t)(lg*2048 + (wn + ntp*16 + l15)*16);

    float acc[2][8][4];

#pragma unroll 1
    for (int y = 0; y < 2; y++) {
        const __half* Abase0 = y ? g_av : g_ah;
        const __half* Bp = y ? g_Wt5 : g_Wt3;
        const __half* scp = (y ? g_scv : g_sch) + (size_t)p0*128;
        const float* biasp = y ? g_b5 : g_b3;
        char* UV = smf + 32768 + y*32768;

#pragma unroll
        for (int mt = 0; mt < 2; mt++)
#pragma unroll
            for (int nt = 0; nt < 8; nt++)
#pragma unroll
                for (int q = 0; q < 4; q++) acc[mt][nt][q] = 0.f;

        auto load_tile = [&](int t, int buf) {
            int k0 = t * 32;
            const __half* asrc = Abase0 + (size_t)p0*128 + k0;
            uint32_t sab = sa_u + (uint32_t)buf*8192;
            uint32_t sbb = sb_u + (uint32_t)buf*8192;
#pragma unroll
            for (int i = 0; i < 2; i++) {
                int id = tid + i*256;
                int o = id & 3, r = id >> 2;
                cpa16(sab + (uint32_t)(o*2048 + r*16), asrc + (size_t)r*128 + o*8);
            }
            const __half* bsrc = Bp + k0;
#pragma unroll
            for (int i = 0; i < 2; i++) {
                int id = tid + i*256;
                int o = id & 3, n = id >> 2;
                cpa16(sbb + (uint32_t)(o*2048 + n*16), bsrc + (size_t)n*128 + o*8);
            }
            CP_COMMIT();
        };

        load_tile(0, 0);
        int buf = 0;
        for (int t = 0; t < 4; t++) {
            CP_WAIT0();
            __syncthreads();
            if (t + 1 < 4) load_tile(t + 1, buf ^ 1);

            uint32_t sab = sa_u + (uint32_t)buf*8192;
            uint32_t sbb = sb_u + (uint32_t)buf*8192;
#pragma unroll
            for (int s = 0; s < 2; s++) {
                uint32_t a[2][4], b[4][4];
#pragma unroll
                for (int mt = 0; mt < 2; mt++)
                    ldm4(a[mt], sab + (uint32_t)s*4096 + aoff[mt]);
#pragma unroll
                for (int ntp = 0; ntp < 4; ntp++)
                    ldm4(b[ntp], sbb + (uint32_t)s*4096 + boff[ntp]);
#pragma unroll
                for (int mt = 0; mt < 2; mt++)
#pragma unroll
                    for (int ntp = 0; ntp < 4; ntp++) {
                        mma_f16(acc[mt][ntp*2 + 0], a[mt], b[ntp][0], b[ntp][2]);
                        mma_f16(acc[mt][ntp*2 + 1], a[mt], b[ntp][1], b[ntp][3]);
                    }
            }
            __syncthreads();
            buf ^= 1;
        }

#pragma unroll
        for (int nt = 0; nt < 8; nt++) {
            int cb = wn + nt*8 + (lane & 3)*2;
            float b0 = biasp[cb], b1 = biasp[cb + 1];
            uint32_t pl = (uint32_t)((cb >> 5)*8192 + ((cb >> 3) & 3)*2048 + (cb & 7)*2);
#pragma unroll
            for (int mt = 0; mt < 2; mt++) {
#pragma unroll
                for (int half = 0; half < 2; half++) {
                    int row = wm + (lane >> 2) + mt*16 + half*8;
                    float2 sc = __half22float2(*(const __half2*)(scp + (size_t)row*128 + cb));
                    float v0 = fmaxf(acc[mt][nt][half*2 + 0] + b0 + sc.x, 0.f);
                    float v1 = fmaxf(acc[mt][nt][half*2 + 1] + b1 + sc.y, 0.f);
                    *(__half2*)(UV + pl + row*16) = __floats2half2_rn(v0, v1);
                }
            }
        }
        __syncthreads();
    }

#pragma unroll
    for (int mt = 0; mt < 2; mt++)
#pragma unroll
        for (int nt = 0; nt < 8; nt++)
#pragma unroll
            for (int q = 0; q < 4; q++) acc[mt][nt][q] = 0.f;

    auto load_B2 = [&](int t, int buf) {
        const __half* bsrc = g_WtF + t*32;
        uint32_t sbb = s_u + (uint32_t)buf*8192;
#pragma unroll
        for (int i = 0; i < 2; i++) {
            int id = tid + i*256;
            int o = id & 3, n = id >> 2;
            cpa16(sbb + (uint32_t)(o*2048 + n*16), bsrc + (size_t)n*256 + o*8);
        }
        CP_COMMIT();
    };

    load_B2(0, 0);
    int buf2 = 0;
    for (int t = 0; t < 8; t++) {
        CP_WAIT0();
        __syncthreads();
        if (t + 1 < 8) load_B2(t + 1, buf2 ^ 1);

        uint32_t abase = uv_u + (uint32_t)((t >> 2)*32768 + (t & 3)*8192);
        uint32_t sbb = s_u + (uint32_t)buf2*8192;
#pragma unroll
        for (int s = 0; s < 2; s++) {
            uint32_t a[2][4], b[4][4];
#pragma unroll
            for (int mt = 0; mt < 2; mt++)
                ldm4(a[mt], abase + (uint32_t)s*4096 + aoff[mt]);
#pragma unroll
            for (int ntp = 0; ntp < 4; ntp++)
                ldm4(b[ntp], sbb + (uint32_t)s*4096 + boff[ntp]);
#pragma unroll
            for (int mt = 0; mt < 2; mt++)
#pragma unroll
                for (int ntp = 0; ntp < 4; ntp++) {
                    mma_f16(acc[mt][ntp*2 + 0], a[mt], b[ntp][0], b[ntp][2]);
                    mma_f16(acc[mt][ntp*2 + 1], a[mt], b[ntp][1], b[ntp][3]);
                }
        }
        __syncthreads();
        buf2 ^= 1;
    }

    {
        const float* biasp = g_ba;
        float* SP = (float*)(smf + 32768);
        const int n_img = p0 / HWD, hw0 = p0 % HWD;
        float* obase = out + (size_t)n_img*CDIM*HWD + hw0;
#pragma unroll
        for (int ch = 0; ch < 2; ch++) {
            if ((wid >> 2) == ch) {
#pragma unroll
                for (int nt = 0; nt < 8; nt++) {
                    int cb = nt*8 + (lane & 3)*2;
                    float b0 = biasp[ch*64 + cb], b1 = biasp[ch*64 + cb + 1];
#pragma unroll
                    for (int mt = 0; mt < 2; mt++)
#pragma unroll
                        for (int half = 0; half < 2; half++) {
                            int row = wm + (lane >> 2) + mt*16 + half*8;
                            SP[cb*129 + row]     = fmaxf(acc[mt][nt][half*2 + 0] + b0, 0.f);
                            SP[(cb+1)*129 + row] = fmaxf(acc[mt][nt][half*2 + 1] + b1, 0.f);
                        }
                }
            }
            __syncthreads();
#pragma unroll
            for (int t2 = 0; t2 < 32; t2++) {
                int id = tid + t2*256;
                int c = id >> 7, pix = id & 127;
                obase[(size_t)(ch*64 + c)*HWD + pix] = SP[c*129 + pix];
            }
            __syncthreads();
        }
    }
}

// ---------------- axial attention: fp16 FA with K/V double-buffered prefetch (unchanged) ----------------
__global__ __launch_bounds__(256, 2) void attn_kernel() {
    extern __shared__ char smc[];
    uint32_t s_u = (uint32_t)__cvta_generic_to_shared(smc);
    uint32_t q_u = s_u, k_u = s_u + 16384, v_u = s_u + 49152, p_u = s_u + 81920;
    float* pmax = (float*)(smc + 90112);
    float* psum = (float*)(smc + 90624);

    const int tid = threadIdx.x;
    const int wid = tid >> 5, lane = tid & 31;
    const int q0 = blockIdx.x * 64;
    const int brow_idx = blockIdx.y;
    const int dir = blockIdx.z;

    size_t base; int stride;
    if (dir == 0) { base = (size_t)brow_idx * LROW * CDIM; stride = CDIM; }
    else {
        int n = brow_idx / WW, w = brow_idx % WW;
        base = (size_t)n*HH*WW*CDIM + (size_t)w*CDIM;
        stride = WW*CDIM;
    }
    const __half* thp = g_th + base;
    const __half* php = g_ph + base;
    const __half* gp  = g_g  + base;
    __half* outp = (dir == 0 ? g_ah : g_av) + base;

    auto fillK = [&](int kb, int buf) {
#pragma unroll
        for (int t = 0; t < 4; t++) {
            int id = tid + t*256;
            int j = id >> 4, g = id & 15;
            cpa16(k_u + (uint32_t)buf*16384 + (uint32_t)(j*256 + ((g ^ (j & 7)) << 4)),
                  php + (size_t)(kb + j)*stride + g*8);
        }
        CP_COMMIT();
    };
    auto fillV = [&](int kb, int buf) {
#pragma unroll
        for (int t = 0; t < 4; t++) {
            int id = tid + t*256;
            int j = id >> 4, g = id & 15;
            cpa16(v_u + (uint32_t)buf*16384 + (uint32_t)(j*256 + ((g ^ (j & 7)) << 4)),
                  gp + (size_t)(kb + j)*stride + g*8);
        }
        CP_COMMIT();
    };

#pragma unroll
    for (int t = 0; t < 4; t++) {
        int id = tid + t*256;
        int i = id >> 4, g = id & 15;
        cpa16(q_u + (uint32_t)(i*256 + ((g ^ (i & 7)) << 4)),
              thp + (size_t)(q0 + i)*stride + g*8);
    }
    CP_COMMIT();
    fillK(0, 0);
    fillV(0, 0);

    const int l15 = lane & 15, lg = lane >> 4;
    const int frow = lane >> 2, fcol2 = (lane & 3)*2;
    const int wm = (wid & 3) * 16;
    const int wnsI = wid >> 2;
    const int wns = wnsI * 32, wnp = wnsI * 64;

    const int rowA = wm + l15;
    const uint32_t qbase = q_u + rowA*256;
    const uint32_t pbase = p_u + rowA*128;
    const int xA = rowA & 7;
    const int rowK0 = wns + l15, rowK1 = wns + 16 + l15;
    const int xK0 = rowK0 & 7, xK1 = rowK1 & 7;
    const int jrow = (lane & 7) + (lane & 8);
    const int jx = lane & 7;
    uint32_t voff[4];
#pragma unroll
    for (int ntp = 0; ntp < 4; ntp++)
        voff[ntp] = (uint32_t)((((wnp >> 3) + ntp*2 + lg) ^ jx) << 4);

    float o[8][4];
#pragma unroll
    for (int nt = 0; nt < 8; nt++)
#pragma unroll
        for (int q = 0; q < 4; q++) o[nt][q] = 0.f;
    float m0 = -1e30f, m1 = -1e30f, l0 = 0.f, l1 = 0.f;
    const float scale = 0.08838834764831845f;

    for (int c = 0; c < 3; c++) {
        const int kb = c*64;
        const uint32_t kcur = k_u + (uint32_t)(c & 1)*16384;
        const uint32_t vcur = v_u + (uint32_t)(c & 1)*16384;

        CP_WAIT1();
        __syncthreads();

        float sacc[4][4];
#pragma unroll
        for (int nt = 0; nt < 4; nt++)
#pragma unroll
            for (int q = 0; q < 4; q++) sacc[nt][q] = 0.f;
        const uint32_t kb0 = kcur + rowK0*256, kb1 = kcur + rowK1*256;
#pragma unroll
        for (int s = 0; s < 8; s++) {
            uint32_t a[4], b0[4], b1[4];
            ldm4(a,  qbase + (uint32_t)(((2*s + lg) ^ xA)  << 4));
            ldm4(b0, kb0   + (uint32_t)(((2*s + lg) ^ xK0) << 4));
            ldm4(b1, kb1   + (uint32_t)(((2*s + lg) ^ xK1) << 4));
            mma_f16(sacc[0], a, b0[0], b0[2]);
            mma_f16(sacc[1], a, b0[1], b0[3]);
            mma_f16(sacc[2], a, b1[0], b1[2]);
            mma_f16(sacc[3], a, b1[1], b1[3]);
        }
        if (c < 2) fillK(kb + 64, (c + 1) & 1);

        float r0 = -1e30f, r1 = -1e30f;
#pragma unroll
        for (int nt = 0; nt < 4; nt++) {
            sacc[nt][0] *= scale; sacc[nt][1] *= scale;
            sacc[nt][2] *= scale; sacc[nt][3] *= scale;
            r0 = fmaxf(r0, fmaxf(sacc[nt][0], sacc[nt][1]));
            r1 = fmaxf(r1, fmaxf(sacc[nt][2], sacc[nt][3]));
        }
        r0 = fmaxf(r0, __shfl_xor_sync(0xffffffffu, r0, 1));
        r0 = fmaxf(r0, __shfl_xor_sync(0xffffffffu, r0, 2));
        r1 = fmaxf(r1, __shfl_xor_sync(0xffffffffu, r1, 1));
        r1 = fmaxf(r1, __shfl_xor_sync(0xffffffffu, r1, 2));
        if ((lane & 3) == 0) {
            pmax[wnsI*64 + wm + frow]     = r0;
            pmax[wnsI*64 + wm + 8 + frow] = r1;
        }
        __syncthreads();

        const int ro0 = wm + frow, ro1 = ro0 + 8;
        float mn0 = fmaxf(m0, fmaxf(pmax[ro0], pmax[64 + ro0]));
        float mn1 = fmaxf(m1, fmaxf(pmax[ro1], pmax[64 + ro1]));
        float al0 = __expf(m0 - mn0), al1 = __expf(m1 - mn1);
        float s0a = 0.f, s1a = 0.f;
#pragma unroll
        for (int nt = 0; nt < 4; nt++) {
            __half2 h01 = __floats2half2_rn(__expf(sacc[nt][0] - mn0), __expf(sacc[nt][1] - mn0));
            __half2 h23 = __floats2half2_rn(__expf(sacc[nt][2] - mn1), __expf(sacc[nt][3] - mn1));
            int jg = wnsI*4 + nt;
            *(__half2*)(smc + 81920 + ro0*128 + ((jg ^ (ro0 & 7)) << 4) + fcol2*2) = h01;
            *(__half2*)(smc + 81920 + ro1*128 + ((jg ^ (ro1 & 7)) << 4) + fcol2*2) = h23;
            float2 e01 = __half22float2(h01), e23 = __half22float2(h23);
            s0a += e01.x + e01.y; s1a += e23.x + e23.y;
        }
        s0a += __shfl_xor_sync(0xffffffffu, s0a, 1);
        s0a += __shfl_xor_sync(0xffffffffu, s0a, 2);
        s1a += __shfl_xor_sync(0xffffffffu, s1a, 1);
        s1a += __shfl_xor_sync(0xffffffffu, s1a, 2);
        if ((lane & 3) == 0) {
            psum[wnsI*64 + ro0] = s0a;
            psum[wnsI*64 + ro1] = s1a;
        }
        if (c < 2) CP_WAIT1(); else CP_WAIT0();
        __syncthreads();

        l0 = l0*al0 + (psum[ro0] + psum[64 + ro0]);
        l1 = l1*al1 + (psum[ro1] + psum[64 + ro1]);
        m0 = mn0; m1 = mn1;
#pragma unroll
        for (int nt = 0; nt < 8; nt++) {
            o[nt][0] *= al0; o[nt][1] *= al0;
            o[nt][2] *= al1; o[nt][3] *= al1;
        }

        const uint32_t vbase = vcur + jrow*256;
#pragma unroll
        for (int s = 0; s < 4; s++) {
            uint32_t pa[4];
            ldm4(pa, pbase + (uint32_t)(((2*s + lg) ^ xA) << 4));
#pragma unroll
            for (int ntp = 0; ntp < 4; ntp++) {
                uint32_t vb[4];
                ldm4t(vb, vbase + (uint32_t)s*4096 + voff[ntp]);
                mma_f16(o[ntp*2 + 0], pa, vb[0], vb[1]);
                mma_f16(o[ntp*2 + 1], pa, vb[2], vb[3]);
            }
        }
        if (c < 2) fillV(kb + 64, (c + 1) & 1);
    }

    {
        float inv0 = 1.f / l0, inv1 = 1.f / l1;
        int r0w = q0 + wm + frow;
#pragma unroll
        for (int nt = 0; nt < 8; nt++) {
            int cb = wnp + nt*8 + fcol2;
            *(__half2*)(outp + (size_t)r0w*stride + cb) =
                __floats2half2_rn(o[nt][0]*inv0, o[nt][1]*inv0);
            *(__half2*)(outp + (size_t)(r0w + 8)*stride + cb) =
                __floats2half2_rn(o[nt][2]*inv1, o[nt][3]*inv1);
        }
    }
}

// ---------------- launch ----------------
extern "C" void kernel_launch(void* const* d_in, const int* in_sizes, int n_in,
                              void* d_out, int out_size) {
    const float* f  = (const float*)d_in[0];
    const float* W7 = (const float*)d_in[1];
    const float* m7 = (const float*)d_in[2];
    const float* v7 = (const float*)d_in[3];
    const float* b7 = (const float*)d_in[4];
    const float* Wa = (const float*)d_in[5];
    const float* ma = (const float*)d_in[6];
    const float* va = (const float*)d_in[7];
    const float* ba = (const float*)d_in[8];
    float* out = (float*)d_out;

    prep_kernel<<<64, 256>>>(W7, m7, v7, b7, Wa, ma, va, ba);

    int smem_g0 = 82944;
    cudaFuncSetAttribute(gemm0_kernel, cudaFuncAttributeMaxDynamicSharedMemorySize, smem_g0);
    gemm0_kernel<<<PTOT/128, 128, smem_g0>>>(f);

    int smem_attn = 91136;
    cudaFuncSetAttribute(attn_kernel, cudaFuncAttributeMaxDynamicSharedMemorySize, smem_attn);
    attn_kernel<<<dim3(LROW/64, NROWS, 2), 256, smem_attn>>>();

    int smem_fused = 98304;
    cudaFuncSetAttribute(fusedc_kernel, cudaFuncAttributeMaxDynamicSharedMemorySize, smem_fused);
    fusedc_kernel<<<PTOT/128, 256, smem_fused>>>(out);
}